// round 12
// baseline (speedup 1.0000x reference)
#include <cuda_runtime.h>
#include <cuda_bf16.h>
#include <cstdint>
#include <math.h>

#define BB 2
#define LL 2048
#define DM 2048
#define NH 16
#define HD 128
#define MROWS (BB*LL)   // 4096
#define WSZ ((size_t)DM*(size_t)DM)

// ---------------------------------------------------------------- scratch ---
__device__ __nv_bfloat16 g_Ah[MROWS*DM];
__device__ __nv_bfloat16 g_Al[MROWS*DM];
__device__ __nv_bfloat16 g_W4h[4*DM*DM];
__device__ __nv_bfloat16 g_W4l[4*DM*DM];
__device__ __nv_bfloat16 g_Qh[MROWS*DM];
__device__ __nv_bfloat16 g_Ql[MROWS*DM];
__device__ __nv_bfloat16 g_Kh[MROWS*DM];
__device__ __nv_bfloat16 g_Kl[MROWS*DM];
__device__ __nv_bfloat16 g_Vh[MROWS*DM];
__device__ __nv_bfloat16 g_Vl[MROWS*DM];

// ------------------------------------------------------------ ptx helpers ---
__device__ __forceinline__ uint32_t smem_u32(const void* p) {
    uint32_t a;
    asm("{ .reg .u64 t; cvta.to.shared.u64 t, %1; cvt.u32.u64 %0, t; }"
        : "=r"(a) : "l"(p));
    return a;
}
__device__ __forceinline__ void cp16(uint32_t d, const void* s) {
    asm volatile("cp.async.cg.shared.global [%0], [%1], 16;" :: "r"(d), "l"(s));
}
__device__ __forceinline__ void cp_commit() {
    asm volatile("cp.async.commit_group;" ::: "memory");
}
template<int N> __device__ __forceinline__ void cp_wait() {
    asm volatile("cp.async.wait_group %0;" :: "n"(N) : "memory");
}
__device__ __forceinline__ void ldm4(uint32_t* r, uint32_t addr) {
    asm volatile("ldmatrix.sync.aligned.m8n8.x4.shared.b16 {%0,%1,%2,%3}, [%4];"
                 : "=r"(r[0]), "=r"(r[1]), "=r"(r[2]), "=r"(r[3]) : "r"(addr));
}
__device__ __forceinline__ void ldm4t(uint32_t* r, uint32_t addr) {
    asm volatile("ldmatrix.sync.aligned.m8n8.x4.trans.shared.b16 {%0,%1,%2,%3}, [%4];"
                 : "=r"(r[0]), "=r"(r[1]), "=r"(r[2]), "=r"(r[3]) : "r"(addr));
}
__device__ __forceinline__ void mma16816(float* c, const uint32_t* a,
                                         const uint32_t* b) {
    asm volatile(
        "mma.sync.aligned.m16n8k16.row.col.f32.bf16.bf16.f32 "
        "{%0,%1,%2,%3}, {%4,%5,%6,%7}, {%8,%9}, {%0,%1,%2,%3};"
        : "+f"(c[0]), "+f"(c[1]), "+f"(c[2]), "+f"(c[3])
        : "r"(a[0]), "r"(a[1]), "r"(a[2]), "r"(a[3]), "r"(b[0]), "r"(b[1]));
}
__device__ __forceinline__ uint32_t pack_hi(float x, float y) {
    __nv_bfloat162 h = __floats2bfloat162_rn(x, y);
    return *(uint32_t*)&h;
}

// ------------------------------------------------------------ split fp32 ----
__device__ __forceinline__ void split_body(const float* __restrict__ src,
                                           __nv_bfloat16* __restrict__ hi,
                                           __nv_bfloat16* __restrict__ lo, int i)
{
    float4 a = ((const float4*)src)[i];
    __nv_bfloat16 h0 = __float2bfloat16(a.x);
    __nv_bfloat16 h1 = __float2bfloat16(a.y);
    __nv_bfloat16 h2 = __float2bfloat16(a.z);
    __nv_bfloat16 h3 = __float2bfloat16(a.w);
    __nv_bfloat16 l0 = __float2bfloat16(a.x - __bfloat162float(h0));
    __nv_bfloat16 l1 = __float2bfloat16(a.y - __bfloat162float(h1));
    __nv_bfloat16 l2 = __float2bfloat16(a.z - __bfloat162float(h2));
    __nv_bfloat16 l3 = __float2bfloat16(a.w - __bfloat162float(h3));
    ((__nv_bfloat162*)hi)[2*i]   = __nv_bfloat162(h0, h1);
    ((__nv_bfloat162*)hi)[2*i+1] = __nv_bfloat162(h2, h3);
    ((__nv_bfloat162*)lo)[2*i]   = __nv_bfloat162(l0, l1);
    ((__nv_bfloat162*)lo)[2*i+1] = __nv_bfloat162(l2, l3);
}

__global__ void __launch_bounds__(256) split_kernel(
    const float* __restrict__ src, __nv_bfloat16* __restrict__ hi,
    __nv_bfloat16* __restrict__ lo, int n4)
{
    int i = blockIdx.x * blockDim.x + threadIdx.x;
    if (i >= n4) return;
    split_body(src, hi, lo, i);
}

__global__ void __launch_bounds__(256) split4_kernel(
    const float* __restrict__ s0, const float* __restrict__ s1,
    const float* __restrict__ s2, const float* __restrict__ s3,
    __nv_bfloat16* __restrict__ hi, __nv_bfloat16* __restrict__ lo, int n4)
{
    int i = blockIdx.x * blockDim.x + threadIdx.x;
    if (i >= n4) return;
    int w = blockIdx.y;
    const float* src = (w == 0) ? s0 : (w == 1) ? s1 : (w == 2) ? s2 : s3;
    split_body(src, hi + (size_t)w * WSZ, lo + (size_t)w * WSZ, i);
}

// --------------------------------------------------- mma.sync bf16 GEMM ----
#define AREG  16384
#define STGB  32768
#define GSTG  3
#define GSMEM (GSTG*STGB)     /* 98304 */

__device__ __forceinline__ void gemm_mainloop(
    const __nv_bfloat16* __restrict__ Ah, const __nv_bfloat16* __restrict__ Al,
    const __nv_bfloat16* __restrict__ Bh, const __nv_bfloat16* __restrict__ Bl,
    uint32_t sb, int tid, int m0, int n0, float acc[4][4][4])
{
    const int lane = tid & 31, wid = tid >> 5;
    const int wm = wid >> 2, wn = wid & 3;
    const int S = DM / 32;

    const int lr = tid >> 1;
    const uint32_t lsx = (uint32_t)(lr & 7) << 4;
    const int lj0 = (tid & 1) * 2;
    const size_t ga = (size_t)(m0 + lr) * DM;
    const size_t gb = (size_t)(n0 + lr) * DM;

    auto load_stage = [&](int s) {
        const int k0 = s * 32;
        const uint32_t ab = sb + (s % GSTG) * STGB + (uint32_t)lr * 128;
        const uint32_t bbs = ab + AREG;
        const char* pah = (const char*)(Ah + ga + k0);
        const char* pal = (const char*)(Al + ga + k0);
        const char* pbh = (const char*)(Bh + gb + k0);
        const char* pbl = (const char*)(Bl + gb + k0);
        #pragma unroll
        for (int q = 0; q < 2; ++q) {
            const int j = lj0 + q;
            cp16(ab  + (((uint32_t)(j    ) << 4) ^ lsx), pah + j*16);
            cp16(ab  + (((uint32_t)(j + 4) << 4) ^ lsx), pal + j*16);
            cp16(bbs + (((uint32_t)(j    ) << 4) ^ lsx), pbh + j*16);
            cp16(bbs + (((uint32_t)(j + 4) << 4) ^ lsx), pbl + j*16);
        }
        cp_commit();
    };

    load_stage(0);
    load_stage(1);

    const uint32_t sx = (uint32_t)(lane & 7) << 4;
    const uint32_t a_row = (uint32_t)(wm*64 + (lane & 15)) * 128;
    const uint32_t a_k   = (uint32_t)(lane >> 4) << 4;
    const uint32_t b_row = (uint32_t)(wn*32 + ((lane >> 4) & 1)*8 + (lane & 7)) * 128;
    const uint32_t b_k   = (uint32_t)((lane >> 3) & 1) << 4;

    for (int s = 0; s < S; ++s) {
        if (s == S - 1) cp_wait<0>(); else cp_wait<1>();
        __syncthreads();
        if (s + 2 < S) load_stage(s + 2);

        const uint32_t Abase = sb + (s % GSTG) * STGB;
        const uint32_t Bbase = Abase + AREG;
        #pragma unroll
        for (int kk = 0; kk < 2; ++kk) {
            const uint32_t kb = (uint32_t)kk * 32;
            uint32_t ah[4][4], bh[2][4];
            #pragma unroll
            for (int i = 0; i < 4; ++i)
                ldm4(ah[i], Abase + a_row + i*2048 + ((kb + a_k) ^ sx));
            #pragma unroll
            for (int p = 0; p < 2; ++p)
                ldm4(bh[p], Bbase + b_row + p*2048 + ((kb + b_k) ^ sx));
            #pragma unroll
            for (int i = 0; i < 4; ++i)
                #pragma unroll
                for (int j = 0; j < 4; ++j)
                    mma16816(acc[i][j], ah[i], &bh[j >> 1][(j & 1) * 2]);
            {
                uint32_t al[4][4];
                #pragma unroll
                for (int i = 0; i < 4; ++i)
                    ldm4(al[i], Abase + a_row + i*2048 + ((64 + kb + a_k) ^ sx));
                #pragma unroll
                for (int i = 0; i < 4; ++i)
                    #pragma unroll
                    for (int j = 0; j < 4; ++j)
                        mma16816(acc[i][j], al[i], &bh[j >> 1][(j & 1) * 2]);
            }
            {
                uint32_t bl[2][4];
                #pragma unroll
                for (int p = 0; p < 2; ++p)
                    ldm4(bl[p], Bbase + b_row + p*2048 + ((64 + kb + b_k) ^ sx));
                #pragma unroll
                for (int i = 0; i < 4; ++i)
                    #pragma unroll
                    for (int j = 0; j < 4; ++j)
                        mma16816(acc[i][j], ah[i], &bl[j >> 1][(j & 1) * 2]);
            }
        }
    }
}

__device__ __forceinline__ void stage_epilogue(char* smem, int tid,
                                               float acc[4][4][4])
{
    __syncthreads();
    float* Cs = (float*)smem;
    const int lane = tid & 31, wid = tid >> 5;
    const int wm = wid >> 2, wn = wid & 3;
    const int frow = wm*64 + (lane >> 2);
    const int fcol = wn*32 + (lane & 3) * 2;
    #pragma unroll
    for (int i = 0; i < 4; ++i)
        #pragma unroll
        for (int j = 0; j < 4; ++j) {
            *(float2*)&Cs[(frow + i*16    )*132 + fcol + j*8] =
                make_float2(acc[i][j][0], acc[i][j][1]);
            *(float2*)&Cs[(frow + i*16 + 8)*132 + fcol + j*8] =
                make_float2(acc[i][j][2], acc[i][j][3]);
        }
    __syncthreads();
}

// ---- fused QKV projection: grid.z selects weight / dst / RoPE ----
__global__ void __launch_bounds__(256, 2) gemm_qkv(
    const __nv_bfloat16* __restrict__ Ah, const __nv_bfloat16* __restrict__ Al,
    const __nv_bfloat16* __restrict__ W4h, const __nv_bfloat16* __restrict__ W4l,
    __nv_bfloat16* __restrict__ Qh, __nv_bfloat16* __restrict__ Ql,
    __nv_bfloat16* __restrict__ Kh, __nv_bfloat16* __restrict__ Kl,
    __nv_bfloat16* __restrict__ Vh, __nv_bfloat16* __restrict__ Vl,
    const float* __restrict__ cosc, const float* __restrict__ sinc)
{
    extern __shared__ char smem[];
    const uint32_t sb = smem_u32(smem);
    const int tid = threadIdx.x;
    const int m0 = blockIdx.y * 128, n0 = blockIdx.x * 128;
    const int z = blockIdx.z;

    const __nv_bfloat16* Bh = W4h + (size_t)z * WSZ;
    const __nv_bfloat16* Bl = W4l + (size_t)z * WSZ;

    float acc[4][4][4];
    #pragma unroll
    for (int i = 0; i < 4; ++i)
        #pragma unroll
        for (int j = 0; j < 4; ++j)
            #pragma unroll
            for (int q = 0; q < 4; ++q) acc[i][j][q] = 0.f;

    gemm_mainloop(Ah, Al, Bh, Bl, sb, tid, m0, n0, acc);
    stage_epilogue(smem, tid, acc);

    __nv_bfloat16 *Ch, *Cl;
    if (z == 0)      { Ch = Qh; Cl = Ql; }
    else if (z == 1) { Ch = Kh; Cl = Kl; }
    else             { Ch = Vh; Cl = Vl; }
    const bool dorope = (z < 2);

    float* Cs = (float*)smem;
    const int row  = tid >> 1;
    const int half = tid & 1;
    const int grow = m0 + row;
    const int h = n0 >> 7;
    int bb = grow >> 11, l = grow & (LL - 1);
    size_t ofs = (((size_t)(bb * NH + h)) * LL + l) * HD;

    #pragma unroll
    for (int c0 = 0; c0 < 32; c0 += 4) {
        const int col = half*32 + c0;
        float a0[4], a1[4];
        #pragma unroll
        for (int q = 0; q < 4; ++q) {
            a0[q] = Cs[row*132 + col + q];
            a1[q] = Cs[row*132 + col + 64 + q];
        }
        if (dorope) {
            #pragma unroll
            for (int q = 0; q < 4; ++q) {
                float c1 = cosc[h*HD + col + q];
                float s1 = sinc[h*HD + col + q];
                float c2 = cosc[h*HD + col + q + 64];
                float s2 = sinc[h*HD + col + q + 64];
                float v0 = a0[q], v1 = a1[q];
                a0[q] = v0*c1 - v1*s1;
                a1[q] = v1*c2 + v0*s2;
            }
        }
        #pragma unroll
        for (int q = 0; q < 4; q += 2) {
            __nv_bfloat162 h0 = __floats2bfloat162_rn(a0[q], a0[q+1]);
            float2 f0 = __bfloat1622float2(h0);
            __nv_bfloat162 l0 = __floats2bfloat162_rn(a0[q]-f0.x, a0[q+1]-f0.y);
            *(__nv_bfloat162*)(Ch + ofs + col + q) = h0;
            *(__nv_bfloat162*)(Cl + ofs + col + q) = l0;
            __nv_bfloat162 h1 = __floats2bfloat162_rn(a1[q], a1[q+1]);
            float2 f1 = __bfloat1622float2(h1);
            __nv_bfloat162 l1 = __floats2bfloat162_rn(a1[q]-f1.x, a1[q+1]-f1.y);
            *(__nv_bfloat162*)(Ch + ofs + col + 64 + q) = h1;
            *(__nv_bfloat162*)(Cl + ofs + col + 64 + q) = l1;
        }
    }
}

// ---- O-projection: fp32 output ----
__global__ void __launch_bounds__(256, 2) gemm_out(
    const __nv_bfloat16* __restrict__ Ah, const __nv_bfloat16* __restrict__ Al,
    const __nv_bfloat16* __restrict__ Bh, const __nv_bfloat16* __restrict__ Bl,
    float* __restrict__ C)
{
    extern __shared__ char smem[];
    const uint32_t sb = smem_u32(smem);
    const int tid = threadIdx.x;
    const int m0 = blockIdx.y * 128, n0 = blockIdx.x * 128;

    float acc[4][4][4];
    #pragma unroll
    for (int i = 0; i < 4; ++i)
        #pragma unroll
        for (int j = 0; j < 4; ++j)
            #pragma unroll
            for (int q = 0; q < 4; ++q) acc[i][j][q] = 0.f;

    gemm_mainloop(Ah, Al, Bh, Bl, sb, tid, m0, n0, acc);
    stage_epilogue(smem, tid, acc);

    float* Cs = (float*)smem;
    const int row  = tid >> 1;
    const int half = tid & 1;
    float* dst = C + (size_t)(m0 + row) * DM + n0;
    #pragma unroll
    for (int c0 = 0; c0 < 32; c0 += 4) {
        const int col = half*32 + c0;
        *(float4*)(dst + col)      = *(float4*)&Cs[row*132 + col];
        *(float4*)(dst + col + 64) = *(float4*)&Cs[row*132 + col + 64];
    }
}

// ---------------------------------------------------- bf16 flash attention --
// q-tile 64, 256 threads / 8 warps (4 rowg x 2 key-half), single-buffered KV,
// 105KB smem -> 2 CTAs/SM (phase-offset CTAs overlap MMA with softmax/loads).
#define APITCH 272
#define QLO    17408
#define AT_K   34816              /* K hi; K lo at +QLO */
#define AT_V   69632              /* V hi; V lo at +QLO */
#define AT_MASK 104448            /* 2048 bytes (uchar) */
#define AT_RED  106496            /* pmax[64][2], psum[64][2] */
#define AT_SMEM 107520

__global__ void __launch_bounds__(256, 2) attn_mma(
    const __nv_bfloat16* __restrict__ Qh, const __nv_bfloat16* __restrict__ Ql,
    const __nv_bfloat16* __restrict__ Kh, const __nv_bfloat16* __restrict__ Kl,
    const __nv_bfloat16* __restrict__ Vh, const __nv_bfloat16* __restrict__ Vl,
    const int* __restrict__ mask,
    __nv_bfloat16* __restrict__ Oh, __nv_bfloat16* __restrict__ Ol)
{
    extern __shared__ char sm[];
    const uint32_t sb = smem_u32(sm);
    const int tid = threadIdx.x, lane = tid & 31, wid = tid >> 5;
    const int rowg = wid >> 1;            // 0..3: 16-row group
    const int half = wid & 1;             // key half (32 cols)
    const int q0 = (int)(gridDim.x - 1 - blockIdx.x) * 64;   // heavy first
    const int h = blockIdx.y, b = blockIdx.z;
    const size_t hb = ((size_t)(b*NH + h)) * LL * HD;
    const __nv_bfloat16 *pQh = Qh+hb, *pQl = Ql+hb;
    const __nv_bfloat16 *pKh = Kh+hb, *pKl = Kl+hb;
    const __nv_bfloat16 *pVh = Vh+hb, *pVl = Vl+hb;
    unsigned char* msk = (unsigned char*)(sm + AT_MASK);
    float* pmax = (float*)(sm + AT_RED);      // [64][2]
    float* psum = pmax + 128;                 // [64][2]

    for (int i = tid; i < LL; i += 256)
        msk[i] = (unsigned char)(mask[b*LL + i] != 0);

    // Q tile (64 rows x 128 hd, hi+lo): 8 cp16 per thread
    {
        int row = tid >> 2;
        int c0 = tid & 3;
        const char* gqh = (const char*)(pQh + (size_t)(q0+row)*HD);
        const char* gql = (const char*)(pQl + (size_t)(q0+row)*HD);
        uint32_t dq = sb + row * APITCH;
        #pragma unroll
        for (int t = 0; t < 4; ++t) {
            int c = c0 + 4*t;
            cp16(dq + c*16,       gqh + c*16);
            cp16(dq + QLO + c*16, gql + c*16);
        }
    }

    auto load_kv = [&](int kt) {
        int k0 = kt * 64;
        int row = tid >> 2;          // 0..63
        int c0 = tid & 3;
        const char* gkh = (const char*)(pKh + (size_t)(k0+row)*HD);
        const char* gkl = (const char*)(pKl + (size_t)(k0+row)*HD);
        const char* gvh = (const char*)(pVh + (size_t)(k0+row)*HD);
        const char* gvl = (const char*)(pVl + (size_t)(k0+row)*HD);
        uint32_t dk = sb + AT_K + row*APITCH;
        uint32_t dv = sb + AT_V + row*APITCH;
        #pragma unroll
        for (int t = 0; t < 4; ++t) {
            int c = c0 + 4*t;
            cp16(dk + c*16,       gkh + c*16);
            cp16(dk + QLO + c*16, gkl + c*16);
            cp16(dv + c*16,       gvh + c*16);
            cp16(dv + QLO + c*16, gvl + c*16);
        }
        cp_commit();
    };

    const int ntiles = q0/64 + 1;
    load_kv(0);

    float oacc[16][4];
    #pragma unroll
    for (int u = 0; u < 16; ++u)
        #pragma unroll
        for (int q = 0; q < 4; ++q) oacc[u][q] = 0.f;
    float m_i[2] = {-1e30f, -1e30f}, l_i[2] = {0.f, 0.f};

    const uint32_t a_hi = sb + (rowg*16 + (lane & 15))*APITCH + (lane >> 4)*16;
    const uint32_t a_lo = a_hi + QLO;
    const uint32_t b_off = (uint32_t)((half*32 + ((lane >> 4) & 1)*8 + (lane & 7))*APITCH
                                      + ((lane >> 3) & 1)*16);
    const uint32_t v_off = (uint32_t)((lane & 15)*APITCH + (lane >> 4)*16);
    const float scale = 0.08838834764831845f;   // 1/sqrt(128)
    const int r0 = lane >> 2;
    const int bar_id = rowg + 1;

    for (int kt = 0; kt < ntiles; ++kt) {
        const int k0 = kt * 64;
        cp_wait<0>();
        __syncthreads();

        const uint32_t kh_base = sb + AT_K;
        const uint32_t vh_base = sb + AT_V;

        // ---- S = Q K^T, warp's 32-key half (3-term) ----
        float sacc[4][4];
        #pragma unroll
        for (int j = 0; j < 4; ++j)
            #pragma unroll
            for (int q = 0; q < 4; ++q) sacc[j][q] = 0.f;

        #pragma unroll 2
        for (int ks = 0; ks < 8; ++ks) {
            const uint32_t ka = ks * 32;
            uint32_t ah[4], al[4], bh[2][4];
            ldm4(ah, a_hi + ka);
            ldm4(al, a_lo + ka);
            #pragma unroll
            for (int p = 0; p < 2; ++p)
                ldm4(bh[p], kh_base + b_off + p*16*APITCH + ka);
            #pragma unroll
            for (int j = 0; j < 4; ++j) {
                uint32_t* bb = &bh[j >> 1][(j & 1) * 2];
                mma16816(sacc[j], ah, bb);
                mma16816(sacc[j], al, bb);
            }
            uint32_t bl[2][4];
            #pragma unroll
            for (int p = 0; p < 2; ++p)
                ldm4(bl[p], kh_base + QLO + b_off + p*16*APITCH + ka);
            #pragma unroll
            for (int j = 0; j < 4; ++j)
                mma16816(sacc[j], ah, &bl[j >> 1][(j & 1) * 2]);
        }

        // ---- softmax: mask + partial max ----
        #pragma unroll
        for (int rr = 0; rr < 2; ++rr) {
            const int lr = rowg*16 + r0 + rr*8;
            const int qr = q0 + lr;
            float tm = -1e30f;
            #pragma unroll
            for (int j = 0; j < 4; ++j) {
                #pragma unroll
                for (int e = 0; e < 2; ++e) {
                    int col = k0 + half*32 + j*8 + (lane & 3)*2 + e;
                    float v = sacc[j][rr*2 + e] * scale;
                    if (col > qr || msk[col] == 0) v = -1e15f;
                    sacc[j][rr*2 + e] = v;
                    tm = fmaxf(tm, v);
                }
            }
            tm = fmaxf(tm, __shfl_xor_sync(0xffffffffu, tm, 1));
            tm = fmaxf(tm, __shfl_xor_sync(0xffffffffu, tm, 2));
            if ((lane & 3) == 0) pmax[lr*2 + half] = tm;
        }
        asm volatile("bar.sync %0, 64;" :: "r"(bar_id) : "memory");

        // ---- combined max, exp, partial sum ----
        float scv[2];
        #pragma unroll
        for (int rr = 0; rr < 2; ++rr) {
            const int lr = rowg*16 + r0 + rr*8;
            float tm = fmaxf(pmax[lr*2], pmax[lr*2 + 1]);
            float mnew = fmaxf(m_i[rr], tm);
            scv[rr] = __expf(m_i[rr] - mnew);
            m_i[rr] = mnew;
            float rs = 0.f;
            #pragma unroll
            for (int j = 0; j < 4; ++j) {
                #pragma unroll
                for (int e = 0; e < 2; ++e) {
                    float p = __expf(sacc[j][rr*2 + e] - mnew);
                    sacc[j][rr*2 + e] = p;
                    rs += p;
                }
            }
            rs += __shfl_xor_sync(0xffffffffu, rs, 1);
            rs += __shfl_xor_sync(0xffffffffu, rs, 2);
            if ((lane & 3) == 0) psum[lr*2 + half] = rs;
            #pragma unroll
            for (int u = 0; u < 16; ++u) {
                oacc[u][rr*2]     *= scv[rr];
                oacc[u][rr*2 + 1] *= scv[rr];
            }
        }
        asm volatile("bar.sync %0, 64;" :: "r"(bar_id) : "memory");

        #pragma unroll
        for (int rr = 0; rr < 2; ++rr) {
            const int lr = rowg*16 + r0 + rr*8;
            l_i[rr] = l_i[rr] * scv[rr] + psum[lr*2] + psum[lr*2 + 1];
        }

        // ---- O += P V over warp's 32 keys (3-term; P split in-register) ----
        #pragma unroll 1
        for (int t = 0; t < 2; ++t) {
            uint32_t pah[4], pal[4];
            #pragma unroll
            for (int idx = 0; idx < 4; ++idx) {
                int j = 2*t + (idx >> 1);
                int o = (idx & 1) * 2;
                float p0 = sacc[j][o], p1 = sacc[j][o + 1];
                __nv_bfloat162 hv = __floats2bfloat162_rn(p0, p1);
                float2 hf = __bfloat1622float2(hv);
                pah[idx] = *(uint32_t*)&hv;
                pal[idx] = pack_hi(p0 - hf.x, p1 - hf.y);
            }
            #pragma unroll
            for (int u = 0; u < 8; ++u) {
                uint32_t vh[4], vl[4];
                uint32_t addr = vh_base + (half*32 + t*16)*APITCH + u*32 + v_off;
                ldm4t(vh, addr);
                ldm4t(vl, addr + QLO);
                mma16816(oacc[2*u],     pah, vh);
                mma16816(oacc[2*u],     pal, vh);
                mma16816(oacc[2*u],     pah, vl);
                mma16816(oacc[2*u + 1], pah, vh + 2);
                mma16816(oacc[2*u + 1], pal, vh + 2);
                mma16816(oacc[2*u + 1], pah, vl + 2);
            }
        }

        __syncthreads();              // all warps done reading KV
        if (kt + 1 < ntiles) load_kv(kt + 1);
    }

    // ---- combine key-halves via smem (reuse K/V region), then epilogue ----
    float* Osm = (float*)(sm + AT_K);       // 64 x 128 fp32 = 32KB
    if (half == 1) {
        #pragma unroll
        for (int rr = 0; rr < 2; ++rr) {
            int r = rowg*16 + r0 + rr*8;
            #pragma unroll
            for (int u = 0; u < 16; ++u) {
                int col = u*8 + (lane & 3)*2;
                Osm[r*128 + col]     = oacc[u][rr*2];
                Osm[r*128 + col + 1] = oacc[u][rr*2 + 1];
            }
        }
    }
    __syncthreads();
    if (half == 0) {
        #pragma unroll
        for (int rr = 0; rr < 2; ++rr) {
            float inv = 1.0f / l_i[rr];
            int r = rowg*16 + r0 + rr*8;
            int lrow = q0 + r;
            size_t base = ((size_t)(b*LL + lrow)) * DM + h*HD;
            #pragma unroll
            for (int u = 0; u < 16; ++u) {
                int col = u*8 + (lane & 3)*2;
                float p0 = (oacc[u][rr*2]     + Osm[r*128 + col])     * inv;
                float p1 = (oacc[u][rr*2 + 1] + Osm[r*128 + col + 1]) * inv;
                __nv_bfloat162 hv = __floats2bfloat162_rn(p0, p1);
                float2 hf = __bfloat1622float2(hv);
                __nv_bfloat162 lv = __floats2bfloat162_rn(p0 - hf.x, p1 - hf.y);
                *(__nv_bfloat162*)(Oh + base + col) = hv;
                *(__nv_bfloat162*)(Ol + base + col) = lv;
            }
        }
    }
}

// ---------------------------------------------------------------------------
extern "C" void kernel_launch(void* const* d_in, const int* in_sizes, int n_in,
                              void* d_out, int out_size)
{
    const float* hidden = (const float*)d_in[0];
    const int*   mask   = (const int*)  d_in[1];
    const float* Wq     = (const float*)d_in[2];
    const float* Wk     = (const float*)d_in[3];
    const float* Wv     = (const float*)d_in[4];
    const float* Wo     = (const float*)d_in[5];
    const float* cosc   = (const float*)d_in[6];
    const float* sinc   = (const float*)d_in[7];
    float* out = (float*)d_out;

    __nv_bfloat16 *Ahp, *Alp, *W4hp, *W4lp, *Qhp, *Qlp, *Khp, *Klp, *Vhp, *Vlp;
    cudaGetSymbolAddress((void**)&Ahp,  g_Ah);
    cudaGetSymbolAddress((void**)&Alp,  g_Al);
    cudaGetSymbolAddress((void**)&W4hp, g_W4h);
    cudaGetSymbolAddress((void**)&W4lp, g_W4l);
    cudaGetSymbolAddress((void**)&Qhp,  g_Qh);
    cudaGetSymbolAddress((void**)&Qlp,  g_Ql);
    cudaGetSymbolAddress((void**)&Khp,  g_Kh);
    cudaGetSymbolAddress((void**)&Klp,  g_Kl);
    cudaGetSymbolAddress((void**)&Vhp,  g_Vh);
    cudaGetSymbolAddress((void**)&Vlp,  g_Vl);

    cudaFuncSetAttribute(gemm_qkv, cudaFuncAttributeMaxDynamicSharedMemorySize, GSMEM);
    cudaFuncSetAttribute(gemm_out, cudaFuncAttributeMaxDynamicSharedMemorySize, GSMEM);
    cudaFuncSetAttribute(attn_mma, cudaFuncAttributeMaxDynamicSharedMemorySize, AT_SMEM);

    const int nA4 = MROWS*DM/4, nW4 = DM*DM/4;

    split_kernel<<<(nA4+255)/256, 256>>>(hidden, Ahp, Alp, nA4);
    {
        dim3 gs((nW4+255)/256, 4);
        split4_kernel<<<gs, 256>>>(Wq, Wk, Wv, Wo, W4hp, W4lp, nW4);
    }

    {
        dim3 gg(DM/128, MROWS/128, 3);
        gemm_qkv<<<gg, 256, GSMEM>>>(Ahp, Alp, W4hp, W4lp,
                                     Qhp, Qlp, Khp, Klp, Vhp, Vlp, cosc, sinc);
    }

    dim3 ga(LL/64, NH, BB);
    attn_mma<<<ga, 256, AT_SMEM>>>(Qhp, Qlp, Khp, Klp, Vhp, Vlp, mask, Ahp, Alp);

    {
        dim3 gg(DM/128, MROWS/128);
        gemm_out<<<gg, 256, GSMEM>>>(Ahp, Alp, W4hp + 3*WSZ, W4lp + 3*WSZ, out);
    }
}

// round 13
// speedup vs baseline: 1.0149x; 1.0149x over previous
#include <cuda_runtime.h>
#include <cuda_bf16.h>
#include <cstdint>
#include <math.h>

#define BB 2
#define LL 2048
#define DM 2048
#define NH 16
#define HD 128
#define MROWS (BB*LL)   // 4096
#define WSZ ((size_t)DM*(size_t)DM)

// ---------------------------------------------------------------- scratch ---
__device__ __nv_bfloat16 g_Ah[MROWS*DM];
__device__ __nv_bfloat16 g_Al[MROWS*DM];
__device__ __nv_bfloat16 g_W4h[4*DM*DM];
__device__ __nv_bfloat16 g_W4l[4*DM*DM];
__device__ __nv_bfloat16 g_Qh[MROWS*DM];
__device__ __nv_bfloat16 g_Ql[MROWS*DM];
__device__ __nv_bfloat16 g_Kh[MROWS*DM];
__device__ __nv_bfloat16 g_Kl[MROWS*DM];
__device__ __nv_bfloat16 g_Vh[MROWS*DM];
__device__ __nv_bfloat16 g_Vl[MROWS*DM];

// ------------------------------------------------------------ ptx helpers ---
__device__ __forceinline__ uint32_t smem_u32(const void* p) {
    uint32_t a;
    asm("{ .reg .u64 t; cvta.to.shared.u64 t, %1; cvt.u32.u64 %0, t; }"
        : "=r"(a) : "l"(p));
    return a;
}
__device__ __forceinline__ void cp16(uint32_t d, const void* s) {
    asm volatile("cp.async.cg.shared.global [%0], [%1], 16;" :: "r"(d), "l"(s));
}
__device__ __forceinline__ void cp_commit() {
    asm volatile("cp.async.commit_group;" ::: "memory");
}
template<int N> __device__ __forceinline__ void cp_wait() {
    asm volatile("cp.async.wait_group %0;" :: "n"(N) : "memory");
}
__device__ __forceinline__ void ldm4(uint32_t* r, uint32_t addr) {
    asm volatile("ldmatrix.sync.aligned.m8n8.x4.shared.b16 {%0,%1,%2,%3}, [%4];"
                 : "=r"(r[0]), "=r"(r[1]), "=r"(r[2]), "=r"(r[3]) : "r"(addr));
}
__device__ __forceinline__ void ldm4t(uint32_t* r, uint32_t addr) {
    asm volatile("ldmatrix.sync.aligned.m8n8.x4.trans.shared.b16 {%0,%1,%2,%3}, [%4];"
                 : "=r"(r[0]), "=r"(r[1]), "=r"(r[2]), "=r"(r[3]) : "r"(addr));
}
__device__ __forceinline__ void mma16816(float* c, const uint32_t* a,
                                         const uint32_t* b) {
    asm volatile(
        "mma.sync.aligned.m16n8k16.row.col.f32.bf16.bf16.f32 "
        "{%0,%1,%2,%3}, {%4,%5,%6,%7}, {%8,%9}, {%0,%1,%2,%3};"
        : "+f"(c[0]), "+f"(c[1]), "+f"(c[2]), "+f"(c[3])
        : "r"(a[0]), "r"(a[1]), "r"(a[2]), "r"(a[3]), "r"(b[0]), "r"(b[1]));
}
__device__ __forceinline__ uint32_t pack_hi(float x, float y) {
    __nv_bfloat162 h = __floats2bfloat162_rn(x, y);
    return *(uint32_t*)&h;
}

// ------------------------------------------------------------ split fp32 ----
__device__ __forceinline__ void split_body(const float* __restrict__ src,
                                           __nv_bfloat16* __restrict__ hi,
                                           __nv_bfloat16* __restrict__ lo, int i)
{
    float4 a = ((const float4*)src)[i];
    __nv_bfloat16 h0 = __float2bfloat16(a.x);
    __nv_bfloat16 h1 = __float2bfloat16(a.y);
    __nv_bfloat16 h2 = __float2bfloat16(a.z);
    __nv_bfloat16 h3 = __float2bfloat16(a.w);
    __nv_bfloat16 l0 = __float2bfloat16(a.x - __bfloat162float(h0));
    __nv_bfloat16 l1 = __float2bfloat16(a.y - __bfloat162float(h1));
    __nv_bfloat16 l2 = __float2bfloat16(a.z - __bfloat162float(h2));
    __nv_bfloat16 l3 = __float2bfloat16(a.w - __bfloat162float(h3));
    ((__nv_bfloat162*)hi)[2*i]   = __nv_bfloat162(h0, h1);
    ((__nv_bfloat162*)hi)[2*i+1] = __nv_bfloat162(h2, h3);
    ((__nv_bfloat162*)lo)[2*i]   = __nv_bfloat162(l0, l1);
    ((__nv_bfloat162*)lo)[2*i+1] = __nv_bfloat162(l2, l3);
}

__global__ void __launch_bounds__(256) split_kernel(
    const float* __restrict__ src, __nv_bfloat16* __restrict__ hi,
    __nv_bfloat16* __restrict__ lo, int n4)
{
    int i = blockIdx.x * blockDim.x + threadIdx.x;
    if (i >= n4) return;
    split_body(src, hi, lo, i);
}

__global__ void __launch_bounds__(256) split4_kernel(
    const float* __restrict__ s0, const float* __restrict__ s1,
    const float* __restrict__ s2, const float* __restrict__ s3,
    __nv_bfloat16* __restrict__ hi, __nv_bfloat16* __restrict__ lo, int n4)
{
    int i = blockIdx.x * blockDim.x + threadIdx.x;
    if (i >= n4) return;
    int w = blockIdx.y;
    const float* src = (w == 0) ? s0 : (w == 1) ? s1 : (w == 2) ? s2 : s3;
    split_body(src, hi + (size_t)w * WSZ, lo + (size_t)w * WSZ, i);
}

// --------------------------------------------------- mma.sync bf16 GEMM ----
#define AREG  16384
#define STGB  32768
#define GSTG  3
#define GSMEM (GSTG*STGB)     /* 98304 */

__device__ __forceinline__ void gemm_mainloop(
    const __nv_bfloat16* __restrict__ Ah, const __nv_bfloat16* __restrict__ Al,
    const __nv_bfloat16* __restrict__ Bh, const __nv_bfloat16* __restrict__ Bl,
    uint32_t sb, int tid, int m0, int n0, float acc[4][4][4])
{
    const int lane = tid & 31, wid = tid >> 5;
    const int wm = wid >> 2, wn = wid & 3;
    const int S = DM / 32;

    const int lr = tid >> 1;
    const uint32_t lsx = (uint32_t)(lr & 7) << 4;
    const int lj0 = (tid & 1) * 2;
    const size_t ga = (size_t)(m0 + lr) * DM;
    const size_t gb = (size_t)(n0 + lr) * DM;

    auto load_stage = [&](int s) {
        const int k0 = s * 32;
        const uint32_t ab = sb + (s % GSTG) * STGB + (uint32_t)lr * 128;
        const uint32_t bbs = ab + AREG;
        const char* pah = (const char*)(Ah + ga + k0);
        const char* pal = (const char*)(Al + ga + k0);
        const char* pbh = (const char*)(Bh + gb + k0);
        const char* pbl = (const char*)(Bl + gb + k0);
        #pragma unroll
        for (int q = 0; q < 2; ++q) {
            const int j = lj0 + q;
            cp16(ab  + (((uint32_t)(j    ) << 4) ^ lsx), pah + j*16);
            cp16(ab  + (((uint32_t)(j + 4) << 4) ^ lsx), pal + j*16);
            cp16(bbs + (((uint32_t)(j    ) << 4) ^ lsx), pbh + j*16);
            cp16(bbs + (((uint32_t)(j + 4) << 4) ^ lsx), pbl + j*16);
        }
        cp_commit();
    };

    load_stage(0);
    load_stage(1);

    const uint32_t sx = (uint32_t)(lane & 7) << 4;
    const uint32_t a_row = (uint32_t)(wm*64 + (lane & 15)) * 128;
    const uint32_t a_k   = (uint32_t)(lane >> 4) << 4;
    const uint32_t b_row = (uint32_t)(wn*32 + ((lane >> 4) & 1)*8 + (lane & 7)) * 128;
    const uint32_t b_k   = (uint32_t)((lane >> 3) & 1) << 4;

    for (int s = 0; s < S; ++s) {
        if (s == S - 1) cp_wait<0>(); else cp_wait<1>();
        __syncthreads();
        if (s + 2 < S) load_stage(s + 2);

        const uint32_t Abase = sb + (s % GSTG) * STGB;
        const uint32_t Bbase = Abase + AREG;
        #pragma unroll
        for (int kk = 0; kk < 2; ++kk) {
            const uint32_t kb = (uint32_t)kk * 32;
            uint32_t ah[4][4], bh[2][4];
            #pragma unroll
            for (int i = 0; i < 4; ++i)
                ldm4(ah[i], Abase + a_row + i*2048 + ((kb + a_k) ^ sx));
            #pragma unroll
            for (int p = 0; p < 2; ++p)
                ldm4(bh[p], Bbase + b_row + p*2048 + ((kb + b_k) ^ sx));
            #pragma unroll
            for (int i = 0; i < 4; ++i)
                #pragma unroll
                for (int j = 0; j < 4; ++j)
                    mma16816(acc[i][j], ah[i], &bh[j >> 1][(j & 1) * 2]);
            {
                uint32_t al[4][4];
                #pragma unroll
                for (int i = 0; i < 4; ++i)
                    ldm4(al[i], Abase + a_row + i*2048 + ((64 + kb + a_k) ^ sx));
                #pragma unroll
                for (int i = 0; i < 4; ++i)
                    #pragma unroll
                    for (int j = 0; j < 4; ++j)
                        mma16816(acc[i][j], al[i], &bh[j >> 1][(j & 1) * 2]);
            }
            {
                uint32_t bl[2][4];
                #pragma unroll
                for (int p = 0; p < 2; ++p)
                    ldm4(bl[p], Bbase + b_row + p*2048 + ((64 + kb + b_k) ^ sx));
                #pragma unroll
                for (int i = 0; i < 4; ++i)
                    #pragma unroll
                    for (int j = 0; j < 4; ++j)
                        mma16816(acc[i][j], ah[i], &bl[j >> 1][(j & 1) * 2]);
            }
        }
    }
}

__device__ __forceinline__ void stage_epilogue(char* smem, int tid,
                                               float acc[4][4][4])
{
    __syncthreads();
    float* Cs = (float*)smem;
    const int lane = tid & 31, wid = tid >> 5;
    const int wm = wid >> 2, wn = wid & 3;
    const int frow = wm*64 + (lane >> 2);
    const int fcol = wn*32 + (lane & 3) * 2;
    #pragma unroll
    for (int i = 0; i < 4; ++i)
        #pragma unroll
        for (int j = 0; j < 4; ++j) {
            *(float2*)&Cs[(frow + i*16    )*132 + fcol + j*8] =
                make_float2(acc[i][j][0], acc[i][j][1]);
            *(float2*)&Cs[(frow + i*16 + 8)*132 + fcol + j*8] =
                make_float2(acc[i][j][2], acc[i][j][3]);
        }
    __syncthreads();
}

// ---- fused QKV projection: grid.z selects weight / dst / RoPE ----
// Q (z==0) is additionally prescaled by 1/sqrt(HD) so attention skips it.
__global__ void __launch_bounds__(256, 2) gemm_qkv(
    const __nv_bfloat16* __restrict__ Ah, const __nv_bfloat16* __restrict__ Al,
    const __nv_bfloat16* __restrict__ W4h, const __nv_bfloat16* __restrict__ W4l,
    __nv_bfloat16* __restrict__ Qh, __nv_bfloat16* __restrict__ Ql,
    __nv_bfloat16* __restrict__ Kh, __nv_bfloat16* __restrict__ Kl,
    __nv_bfloat16* __restrict__ Vh, __nv_bfloat16* __restrict__ Vl,
    const float* __restrict__ cosc, const float* __restrict__ sinc)
{
    extern __shared__ char smem[];
    const uint32_t sb = smem_u32(smem);
    const int tid = threadIdx.x;
    const int m0 = blockIdx.y * 128, n0 = blockIdx.x * 128;
    const int z = blockIdx.z;

    const __nv_bfloat16* Bh = W4h + (size_t)z * WSZ;
    const __nv_bfloat16* Bl = W4l + (size_t)z * WSZ;

    float acc[4][4][4];
    #pragma unroll
    for (int i = 0; i < 4; ++i)
        #pragma unroll
        for (int j = 0; j < 4; ++j)
            #pragma unroll
            for (int q = 0; q < 4; ++q) acc[i][j][q] = 0.f;

    gemm_mainloop(Ah, Al, Bh, Bl, sb, tid, m0, n0, acc);
    stage_epilogue(smem, tid, acc);

    __nv_bfloat16 *Ch, *Cl;
    if (z == 0)      { Ch = Qh; Cl = Ql; }
    else if (z == 1) { Ch = Kh; Cl = Kl; }
    else             { Ch = Vh; Cl = Vl; }
    const bool dorope = (z < 2);
    const float postscale = (z == 0) ? 0.08838834764831845f : 1.0f;

    float* Cs = (float*)smem;
    const int row  = tid >> 1;
    const int half = tid & 1;
    const int grow = m0 + row;
    const int h = n0 >> 7;
    int bb = grow >> 11, l = grow & (LL - 1);
    size_t ofs = (((size_t)(bb * NH + h)) * LL + l) * HD;

    #pragma unroll
    for (int c0 = 0; c0 < 32; c0 += 4) {
        const int col = half*32 + c0;
        float a0[4], a1[4];
        #pragma unroll
        for (int q = 0; q < 4; ++q) {
            a0[q] = Cs[row*132 + col + q];
            a1[q] = Cs[row*132 + col + 64 + q];
        }
        if (dorope) {
            #pragma unroll
            for (int q = 0; q < 4; ++q) {
                float c1 = cosc[h*HD + col + q];
                float s1 = sinc[h*HD + col + q];
                float c2 = cosc[h*HD + col + q + 64];
                float s2 = sinc[h*HD + col + q + 64];
                float v0 = a0[q], v1 = a1[q];
                a0[q] = (v0*c1 - v1*s1) * postscale;
                a1[q] = (v1*c2 + v0*s2) * postscale;
            }
        }
        #pragma unroll
        for (int q = 0; q < 4; q += 2) {
            __nv_bfloat162 h0 = __floats2bfloat162_rn(a0[q], a0[q+1]);
            float2 f0 = __bfloat1622float2(h0);
            __nv_bfloat162 l0 = __floats2bfloat162_rn(a0[q]-f0.x, a0[q+1]-f0.y);
            *(__nv_bfloat162*)(Ch + ofs + col + q) = h0;
            *(__nv_bfloat162*)(Cl + ofs + col + q) = l0;
            __nv_bfloat162 h1 = __floats2bfloat162_rn(a1[q], a1[q+1]);
            float2 f1 = __bfloat1622float2(h1);
            __nv_bfloat162 l1 = __floats2bfloat162_rn(a1[q]-f1.x, a1[q+1]-f1.y);
            *(__nv_bfloat162*)(Ch + ofs + col + 64 + q) = h1;
            *(__nv_bfloat162*)(Cl + ofs + col + 64 + q) = l1;
        }
    }
}

// ---- O-projection: fp32 output ----
__global__ void __launch_bounds__(256, 2) gemm_out(
    const __nv_bfloat16* __restrict__ Ah, const __nv_bfloat16* __restrict__ Al,
    const __nv_bfloat16* __restrict__ Bh, const __nv_bfloat16* __restrict__ Bl,
    float* __restrict__ C)
{
    extern __shared__ char smem[];
    const uint32_t sb = smem_u32(smem);
    const int tid = threadIdx.x;
    const int m0 = blockIdx.y * 128, n0 = blockIdx.x * 128;

    float acc[4][4][4];
    #pragma unroll
    for (int i = 0; i < 4; ++i)
        #pragma unroll
        for (int j = 0; j < 4; ++j)
            #pragma unroll
            for (int q = 0; q < 4; ++q) acc[i][j][q] = 0.f;

    gemm_mainloop(Ah, Al, Bh, Bl, sb, tid, m0, n0, acc);
    stage_epilogue(smem, tid, acc);

    float* Cs = (float*)smem;
    const int row  = tid >> 1;
    const int half = tid & 1;
    float* dst = C + (size_t)(m0 + row) * DM + n0;
    #pragma unroll
    for (int c0 = 0; c0 < 32; c0 += 4) {
        const int col = half*32 + c0;
        *(float4*)(dst + col)      = *(float4*)&Cs[row*132 + col];
        *(float4*)(dst + col + 64) = *(float4*)&Cs[row*132 + col + 64];
    }
}

// ---------------------------------------------------- bf16 flash attention --
// q-tile 64, 256 threads / 8 warps (4 rowg x 2 key-half), single-buffered KV,
// 2 CTAs/SM. Q comes prescaled. Interior tiles skip masking (uniform branch).
#define APITCH 272
#define QLO    17408
#define AT_K   34816              /* K hi; K lo at +QLO */
#define AT_V   69632              /* V hi; V lo at +QLO */
#define AT_MASK 104448            /* 2048 bytes (uchar) */
#define AT_RED  106496            /* pmax[64][2], psum[64][2] = 1024B */
#define AT_FLAG 107520            /* per-tile all-valid flags, 32B */
#define AT_SMEM 107584

__global__ void __launch_bounds__(256, 2) attn_mma(
    const __nv_bfloat16* __restrict__ Qh, const __nv_bfloat16* __restrict__ Ql,
    const __nv_bfloat16* __restrict__ Kh, const __nv_bfloat16* __restrict__ Kl,
    const __nv_bfloat16* __restrict__ Vh, const __nv_bfloat16* __restrict__ Vl,
    const int* __restrict__ mask,
    __nv_bfloat16* __restrict__ Oh, __nv_bfloat16* __restrict__ Ol)
{
    extern __shared__ char sm[];
    const uint32_t sb = smem_u32(sm);
    const int tid = threadIdx.x, lane = tid & 31, wid = tid >> 5;
    const int rowg = wid >> 1;            // 0..3: 16-row group
    const int half = wid & 1;             // key half (32 cols)
    const int q0 = (int)(gridDim.x - 1 - blockIdx.x) * 64;   // heavy first
    const int h = blockIdx.y, b = blockIdx.z;
    const size_t hb = ((size_t)(b*NH + h)) * LL * HD;
    const __nv_bfloat16 *pQh = Qh+hb, *pQl = Ql+hb;
    const __nv_bfloat16 *pKh = Kh+hb, *pKl = Kl+hb;
    const __nv_bfloat16 *pVh = Vh+hb, *pVl = Vl+hb;
    unsigned char* msk = (unsigned char*)(sm + AT_MASK);
    float* pmax = (float*)(sm + AT_RED);      // [64][2]
    float* psum = pmax + 128;                 // [64][2]
    unsigned char* tflag = (unsigned char*)(sm + AT_FLAG);

    for (int i = tid; i < LL; i += 256)
        msk[i] = (unsigned char)(mask[b*LL + i] != 0);

    // Q tile (64 rows x 128 hd, hi+lo): 8 cp16 per thread
    {
        int row = tid >> 2;
        int c0 = tid & 3;
        const char* gqh = (const char*)(pQh + (size_t)(q0+row)*HD);
        const char* gql = (const char*)(pQl + (size_t)(q0+row)*HD);
        uint32_t dq = sb + row * APITCH;
        #pragma unroll
        for (int t = 0; t < 4; ++t) {
            int c = c0 + 4*t;
            cp16(dq + c*16,       gqh + c*16);
            cp16(dq + QLO + c*16, gql + c*16);
        }
    }

    auto load_kv = [&](int kt) {
        int k0 = kt * 64;
        int row = tid >> 2;          // 0..63
        int c0 = tid & 3;
        const char* gkh = (const char*)(pKh + (size_t)(k0+row)*HD);
        const char* gkl = (const char*)(pKl + (size_t)(k0+row)*HD);
        const char* gvh = (const char*)(pVh + (size_t)(k0+row)*HD);
        const char* gvl = (const char*)(pVl + (size_t)(k0+row)*HD);
        uint32_t dk = sb + AT_K + row*APITCH;
        uint32_t dv = sb + AT_V + row*APITCH;
        #pragma unroll
        for (int t = 0; t < 4; ++t) {
            int c = c0 + 4*t;
            cp16(dk + c*16,       gkh + c*16);
            cp16(dk + QLO + c*16, gkl + c*16);
            cp16(dv + c*16,       gvh + c*16);
            cp16(dv + QLO + c*16, gvl + c*16);
        }
        cp_commit();
    };

    const int ntiles = q0/64 + 1;
    load_kv(0);

    // per-64-key-tile all-valid flags (needs msk complete)
    __syncthreads();
    if (tid < 32) {
        unsigned char f = 1;
        #pragma unroll 8
        for (int j = 0; j < 64; ++j) f &= msk[tid*64 + j];
        tflag[tid] = f;
    }

    float oacc[16][4];
    #pragma unroll
    for (int u = 0; u < 16; ++u)
        #pragma unroll
        for (int q = 0; q < 4; ++q) oacc[u][q] = 0.f;
    float m_i[2] = {-1e30f, -1e30f}, l_i[2] = {0.f, 0.f};

    const uint32_t a_hi = sb + (rowg*16 + (lane & 15))*APITCH + (lane >> 4)*16;
    const uint32_t a_lo = a_hi + QLO;
    const uint32_t b_off = (uint32_t)((half*32 + ((lane >> 4) & 1)*8 + (lane & 7))*APITCH
                                      + ((lane >> 3) & 1)*16);
    const uint32_t v_off = (uint32_t)((lane & 15)*APITCH + (lane >> 4)*16);
    const int r0 = lane >> 2;
    const int bar_id = rowg + 1;

    for (int kt = 0; kt < ntiles; ++kt) {
        const int k0 = kt * 64;
        cp_wait<0>();
        __syncthreads();

        const uint32_t kh_base = sb + AT_K;
        const uint32_t vh_base = sb + AT_V;

        // ---- S = Q K^T, warp's 32-key half (3-term; Q prescaled) ----
        float sacc[4][4];
        #pragma unroll
        for (int j = 0; j < 4; ++j)
            #pragma unroll
            for (int q = 0; q < 4; ++q) sacc[j][q] = 0.f;

        #pragma unroll 2
        for (int ks = 0; ks < 8; ++ks) {
            const uint32_t ka = ks * 32;
            uint32_t ah[4], al[4], bh[2][4];
            ldm4(ah, a_hi + ka);
            ldm4(al, a_lo + ka);
            #pragma unroll
            for (int p = 0; p < 2; ++p)
                ldm4(bh[p], kh_base + b_off + p*16*APITCH + ka);
            #pragma unroll
            for (int j = 0; j < 4; ++j) {
                uint32_t* bb = &bh[j >> 1][(j & 1) * 2];
                mma16816(sacc[j], ah, bb);
                mma16816(sacc[j], al, bb);
            }
            uint32_t bl[2][4];
            #pragma unroll
            for (int p = 0; p < 2; ++p)
                ldm4(bl[p], kh_base + QLO + b_off + p*16*APITCH + ka);
            #pragma unroll
            for (int j = 0; j < 4; ++j)
                mma16816(sacc[j], ah, &bl[j >> 1][(j & 1) * 2]);
        }

        // ---- softmax: (optional) mask + partial max ----
        const bool needmask = (k0 + 64 > q0) || (tflag[kt] == 0);
        #pragma unroll
        for (int rr = 0; rr < 2; ++rr) {
            const int lr = rowg*16 + r0 + rr*8;
            const int qr = q0 + lr;
            float tm = -1e30f;
            if (needmask) {
                #pragma unroll
                for (int j = 0; j < 4; ++j) {
                    #pragma unroll
                    for (int e = 0; e < 2; ++e) {
                        int col = k0 + half*32 + j*8 + (lane & 3)*2 + e;
                        float v = sacc[j][rr*2 + e];
                        if (col > qr || msk[col] == 0) v = -1e15f;
                        sacc[j][rr*2 + e] = v;
                        tm = fmaxf(tm, v);
                    }
                }
            } else {
                #pragma unroll
                for (int j = 0; j < 4; ++j) {
                    tm = fmaxf(tm, fmaxf(sacc[j][rr*2], sacc[j][rr*2 + 1]));
                }
            }
            tm = fmaxf(tm, __shfl_xor_sync(0xffffffffu, tm, 1));
            tm = fmaxf(tm, __shfl_xor_sync(0xffffffffu, tm, 2));
            if ((lane & 3) == 0) pmax[lr*2 + half] = tm;
        }
        asm volatile("bar.sync %0, 64;" :: "r"(bar_id) : "memory");

        // ---- combined max, exp, partial sum ----
        float scv[2];
        #pragma unroll
        for (int rr = 0; rr < 2; ++rr) {
            const int lr = rowg*16 + r0 + rr*8;
            float tm = fmaxf(pmax[lr*2], pmax[lr*2 + 1]);
            float mnew = fmaxf(m_i[rr], tm);
            scv[rr] = __expf(m_i[rr] - mnew);
            m_i[rr] = mnew;
            float rs = 0.f;
            #pragma unroll
            for (int j = 0; j < 4; ++j) {
                #pragma unroll
                for (int e = 0; e < 2; ++e) {
                    float p = __expf(sacc[j][rr*2 + e] - mnew);
                    sacc[j][rr*2 + e] = p;
                    rs += p;
                }
            }
            rs += __shfl_xor_sync(0xffffffffu, rs, 1);
            rs += __shfl_xor_sync(0xffffffffu, rs, 2);
            if ((lane & 3) == 0) psum[lr*2 + half] = rs;
            #pragma unroll
            for (int u = 0; u < 16; ++u) {
                oacc[u][rr*2]     *= scv[rr];
                oacc[u][rr*2 + 1] *= scv[rr];
            }
        }
        asm volatile("bar.sync %0, 64;" :: "r"(bar_id) : "memory");

        #pragma unroll
        for (int rr = 0; rr < 2; ++rr) {
            const int lr = rowg*16 + r0 + rr*8;
            l_i[rr] = l_i[rr] * scv[rr] + psum[lr*2] + psum[lr*2 + 1];
        }

        // ---- O += P V over warp's 32 keys (3-term; P split in-register) ----
        #pragma unroll 1
        for (int t = 0; t < 2; ++t) {
            uint32_t pah[4], pal[4];
            #pragma unroll
            for (int idx = 0; idx < 4; ++idx) {
                int j = 2*t + (idx >> 1);
                int o = (idx & 1) * 2;
                float p0 = sacc[j][o], p1 = sacc[j][o + 1];
                __nv_bfloat162 hv = __floats2bfloat162_rn(p0, p1);
                float2 hf = __bfloat1622float2(hv);
                pah[idx] = *(uint32_t*)&hv;
                pal[idx] = pack_hi(p0 - hf.x, p1 - hf.y);
            }
            #pragma unroll
            for (int u = 0; u < 8; ++u) {
                uint32_t vh[4], vl[4];
                uint32_t addr = vh_base + (half*32 + t*16)*APITCH + u*32 + v_off;
                ldm4t(vh, addr);
                ldm4t(vl, addr + QLO);
                mma16816(oacc[2*u],     pah, vh);
                mma16816(oacc[2*u],     pal, vh);
                mma16816(oacc[2*u],     pah, vl);
                mma16816(oacc[2*u + 1], pah, vh + 2);
                mma16816(oacc[2*u + 1], pal, vh + 2);
                mma16816(oacc[2*u + 1], pah, vl + 2);
            }
        }

        __syncthreads();              // all warps done reading KV
        if (kt + 1 < ntiles) load_kv(kt + 1);
    }

    // ---- combine key-halves via smem (reuse K/V region), then epilogue ----
    float* Osm = (float*)(sm + AT_K);       // 64 x 128 fp32 = 32KB
    if (half == 1) {
        #pragma unroll
        for (int rr = 0; rr < 2; ++rr) {
            int r = rowg*16 + r0 + rr*8;
            #pragma unroll
            for (int u = 0; u < 16; ++u) {
                int col = u*8 + (lane & 3)*2;
                Osm[r*128 + col]     = oacc[u][rr*2];
                Osm[r*128 + col + 1] = oacc[u][rr*2 + 1];
            }
        }
    }
    __syncthreads();
    if (half == 0) {
        #pragma unroll
        for (int rr = 0; rr < 2; ++rr) {
            float inv = 1.0f / l_i[rr];
            int r = rowg*16 + r0 + rr*8;
            int lrow = q0 + r;
            size_t base = ((size_t)(b*LL + lrow)) * DM + h*HD;
            #pragma unroll
            for (int u = 0; u < 16; ++u) {
                int col = u*8 + (lane & 3)*2;
                float p0 = (oacc[u][rr*2]     + Osm[r*128 + col])     * inv;
                float p1 = (oacc[u][rr*2 + 1] + Osm[r*128 + col + 1]) * inv;
                __nv_bfloat162 hv = __floats2bfloat162_rn(p0, p1);
                float2 hf = __bfloat1622float2(hv);
                __nv_bfloat162 lv = __floats2bfloat162_rn(p0 - hf.x, p1 - hf.y);
                *(__nv_bfloat162*)(Oh + base + col) = hv;
                *(__nv_bfloat162*)(Ol + base + col) = lv;
            }
        }
    }
}

// ---------------------------------------------------------------------------
extern "C" void kernel_launch(void* const* d_in, const int* in_sizes, int n_in,
                              void* d_out, int out_size)
{
    const float* hidden = (const float*)d_in[0];
    const int*   mask   = (const int*)  d_in[1];
    const float* Wq     = (const float*)d_in[2];
    const float* Wk     = (const float*)d_in[3];
    const float* Wv     = (const float*)d_in[4];
    const float* Wo     = (const float*)d_in[5];
    const float* cosc   = (const float*)d_in[6];
    const float* sinc   = (const float*)d_in[7];
    float* out = (float*)d_out;

    __nv_bfloat16 *Ahp, *Alp, *W4hp, *W4lp, *Qhp, *Qlp, *Khp, *Klp, *Vhp, *Vlp;
    cudaGetSymbolAddress((void**)&Ahp,  g_Ah);
    cudaGetSymbolAddress((void**)&Alp,  g_Al);
    cudaGetSymbolAddress((void**)&W4hp, g_W4h);
    cudaGetSymbolAddress((void**)&W4lp, g_W4l);
    cudaGetSymbolAddress((void**)&Qhp,  g_Qh);
    cudaGetSymbolAddress((void**)&Qlp,  g_Ql);
    cudaGetSymbolAddress((void**)&Khp,  g_Kh);
    cudaGetSymbolAddress((void**)&Klp,  g_Kl);
    cudaGetSymbolAddress((void**)&Vhp,  g_Vh);
    cudaGetSymbolAddress((void**)&Vlp,  g_Vl);

    cudaFuncSetAttribute(gemm_qkv, cudaFuncAttributeMaxDynamicSharedMemorySize, GSMEM);
    cudaFuncSetAttribute(gemm_out, cudaFuncAttributeMaxDynamicSharedMemorySize, GSMEM);
    cudaFuncSetAttribute(attn_mma, cudaFuncAttributeMaxDynamicSharedMemorySize, AT_SMEM);

    const int nA4 = MROWS*DM/4, nW4 = DM*DM/4;

    split_kernel<<<(nA4+255)/256, 256>>>(hidden, Ahp, Alp, nA4);
    {
        dim3 gs((nW4+255)/256, 4);
        split4_kernel<<<gs, 256>>>(Wq, Wk, Wv, Wo, W4hp, W4lp, nW4);
    }

    {
        dim3 gg(DM/128, MROWS/128, 3);
        gemm_qkv<<<gg, 256, GSMEM>>>(Ahp, Alp, W4hp, W4lp,
                                     Qhp, Qlp, Khp, Klp, Vhp, Vlp, cosc, sinc);
    }

    dim3 ga(LL/64, NH, BB);
    attn_mma<<<ga, 256, AT_SMEM>>>(Qhp, Qlp, Khp, Klp, Vhp, Vlp, mask, Ahp, Alp);

    {
        dim3 gg(DM/128, MROWS/128);
        gemm_out<<<gg, 256, GSMEM>>>(Ahp, Alp, W4hp + 3*WSZ, W4lp + 3*WSZ, out);
    }
}

// round 15
// speedup vs baseline: 1.1824x; 1.1650x over previous
#include <cuda_runtime.h>
#include <cuda_bf16.h>
#include <cuda_fp16.h>
#include <cstdint>
#include <math.h>

#define BB 2
#define LL 2048
#define DM 2048
#define NH 16
#define HD 128
#define MROWS (BB*LL)   // 4096
#define WSZ ((size_t)DM*(size_t)DM)

// ---------------------------------------------------------------- scratch ---
__device__ __nv_bfloat16 g_Ah[MROWS*DM];
__device__ __nv_bfloat16 g_Al[MROWS*DM];
__device__ __nv_bfloat16 g_W4h[4*DM*DM];
__device__ __nv_bfloat16 g_W4l[4*DM*DM];
__device__ __half g_Qf[MROWS*DM];
__device__ __half g_Kf[MROWS*DM];
__device__ __half g_Vf[MROWS*DM];

// ------------------------------------------------------------ ptx helpers ---
__device__ __forceinline__ uint32_t smem_u32(const void* p) {
    uint32_t a;
    asm("{ .reg .u64 t; cvta.to.shared.u64 t, %1; cvt.u32.u64 %0, t; }"
        : "=r"(a) : "l"(p));
    return a;
}
__device__ __forceinline__ void cp16(uint32_t d, const void* s) {
    asm volatile("cp.async.cg.shared.global [%0], [%1], 16;" :: "r"(d), "l"(s));
}
__device__ __forceinline__ void cp_commit() {
    asm volatile("cp.async.commit_group;" ::: "memory");
}
template<int N> __device__ __forceinline__ void cp_wait() {
    asm volatile("cp.async.wait_group %0;" :: "n"(N) : "memory");
}
__device__ __forceinline__ void ldm4(uint32_t* r, uint32_t addr) {
    asm volatile("ldmatrix.sync.aligned.m8n8.x4.shared.b16 {%0,%1,%2,%3}, [%4];"
                 : "=r"(r[0]), "=r"(r[1]), "=r"(r[2]), "=r"(r[3]) : "r"(addr));
}
__device__ __forceinline__ void ldm4t(uint32_t* r, uint32_t addr) {
    asm volatile("ldmatrix.sync.aligned.m8n8.x4.trans.shared.b16 {%0,%1,%2,%3}, [%4];"
                 : "=r"(r[0]), "=r"(r[1]), "=r"(r[2]), "=r"(r[3]) : "r"(addr));
}
__device__ __forceinline__ void mma16816(float* c, const uint32_t* a,
                                         const uint32_t* b) {
    asm volatile(
        "mma.sync.aligned.m16n8k16.row.col.f32.bf16.bf16.f32 "
        "{%0,%1,%2,%3}, {%4,%5,%6,%7}, {%8,%9}, {%0,%1,%2,%3};"
        : "+f"(c[0]), "+f"(c[1]), "+f"(c[2]), "+f"(c[3])
        : "r"(a[0]), "r"(a[1]), "r"(a[2]), "r"(a[3]), "r"(b[0]), "r"(b[1]));
}
__device__ __forceinline__ void mma16816h(float* c, const uint32_t* a,
                                          const uint32_t* b) {
    asm volatile(
        "mma.sync.aligned.m16n8k16.row.col.f32.f16.f16.f32 "
        "{%0,%1,%2,%3}, {%4,%5,%6,%7}, {%8,%9}, {%0,%1,%2,%3};"
        : "+f"(c[0]), "+f"(c[1]), "+f"(c[2]), "+f"(c[3])
        : "r"(a[0]), "r"(a[1]), "r"(a[2]), "r"(a[3]), "r"(b[0]), "r"(b[1]));
}

// ------------------------------------------------------------ split fp32 ----
__device__ __forceinline__ void split_body(const float* __restrict__ src,
                                           __nv_bfloat16* __restrict__ hi,
                                           __nv_bfloat16* __restrict__ lo, int i)
{
    float4 a = ((const float4*)src)[i];
    __nv_bfloat16 h0 = __float2bfloat16(a.x);
    __nv_bfloat16 h1 = __float2bfloat16(a.y);
    __nv_bfloat16 h2 = __float2bfloat16(a.z);
    __nv_bfloat16 h3 = __float2bfloat16(a.w);
    __nv_bfloat16 l0 = __float2bfloat16(a.x - __bfloat162float(h0));
    __nv_bfloat16 l1 = __float2bfloat16(a.y - __bfloat162float(h1));
    __nv_bfloat16 l2 = __float2bfloat16(a.z - __bfloat162float(h2));
    __nv_bfloat16 l3 = __float2bfloat16(a.w - __bfloat162float(h3));
    ((__nv_bfloat162*)hi)[2*i]   = __nv_bfloat162(h0, h1);
    ((__nv_bfloat162*)hi)[2*i+1] = __nv_bfloat162(h2, h3);
    ((__nv_bfloat162*)lo)[2*i]   = __nv_bfloat162(l0, l1);
    ((__nv_bfloat162*)lo)[2*i+1] = __nv_bfloat162(l2, l3);
}

__global__ void __launch_bounds__(256) split_kernel(
    const float* __restrict__ src, __nv_bfloat16* __restrict__ hi,
    __nv_bfloat16* __restrict__ lo, int n4)
{
    int i = blockIdx.x * blockDim.x + threadIdx.x;
    if (i >= n4) return;
    split_body(src, hi, lo, i);
}

__global__ void __launch_bounds__(256) split4_kernel(
    const float* __restrict__ s0, const float* __restrict__ s1,
    const float* __restrict__ s2, const float* __restrict__ s3,
    __nv_bfloat16* __restrict__ hi, __nv_bfloat16* __restrict__ lo, int n4)
{
    int i = blockIdx.x * blockDim.x + threadIdx.x;
    if (i >= n4) return;
    int w = blockIdx.y;
    const float* src = (w == 0) ? s0 : (w == 1) ? s1 : (w == 2) ? s2 : s3;
    split_body(src, hi + (size_t)w * WSZ, lo + (size_t)w * WSZ, i);
}

// --------------------------------------------------- mma.sync bf16 GEMM ----
#define AREG  16384
#define STGB  32768
#define GSTG  3
#define GSMEM (GSTG*STGB)     /* 98304 */

__device__ __forceinline__ void gemm_mainloop(
    const __nv_bfloat16* __restrict__ Ah, const __nv_bfloat16* __restrict__ Al,
    const __nv_bfloat16* __restrict__ Bh, const __nv_bfloat16* __restrict__ Bl,
    uint32_t sb, int tid, int m0, int n0, float acc[4][4][4])
{
    const int lane = tid & 31, wid = tid >> 5;
    const int wm = wid >> 2, wn = wid & 3;
    const int S = DM / 32;

    const int lr = tid >> 1;
    const uint32_t lsx = (uint32_t)(lr & 7) << 4;
    const int lj0 = (tid & 1) * 2;
    const size_t ga = (size_t)(m0 + lr) * DM;
    const size_t gb = (size_t)(n0 + lr) * DM;

    auto load_stage = [&](int s) {
        const int k0 = s * 32;
        const uint32_t ab = sb + (s % GSTG) * STGB + (uint32_t)lr * 128;
        const uint32_t bbs = ab + AREG;
        const char* pah = (const char*)(Ah + ga + k0);
        const char* pal = (const char*)(Al + ga + k0);
        const char* pbh = (const char*)(Bh + gb + k0);
        const char* pbl = (const char*)(Bl + gb + k0);
        #pragma unroll
        for (int q = 0; q < 2; ++q) {
            const int j = lj0 + q;
            cp16(ab  + (((uint32_t)(j    ) << 4) ^ lsx), pah + j*16);
            cp16(ab  + (((uint32_t)(j + 4) << 4) ^ lsx), pal + j*16);
            cp16(bbs + (((uint32_t)(j    ) << 4) ^ lsx), pbh + j*16);
            cp16(bbs + (((uint32_t)(j + 4) << 4) ^ lsx), pbl + j*16);
        }
        cp_commit();
    };

    load_stage(0);
    load_stage(1);

    const uint32_t sx = (uint32_t)(lane & 7) << 4;
    const uint32_t a_row = (uint32_t)(wm*64 + (lane & 15)) * 128;
    const uint32_t a_k   = (uint32_t)(lane >> 4) << 4;
    const uint32_t b_row = (uint32_t)(wn*32 + ((lane >> 4) & 1)*8 + (lane & 7)) * 128;
    const uint32_t b_k   = (uint32_t)((lane >> 3) & 1) << 4;

    for (int s = 0; s < S; ++s) {
        if (s == S - 1) cp_wait<0>(); else cp_wait<1>();
        __syncthreads();
        if (s + 2 < S) load_stage(s + 2);

        const uint32_t Abase = sb + (s % GSTG) * STGB;
        const uint32_t Bbase = Abase + AREG;
        #pragma unroll
        for (int kk = 0; kk < 2; ++kk) {
            const uint32_t kb = (uint32_t)kk * 32;
            uint32_t ah[4][4], bh[2][4];
            #pragma unroll
            for (int i = 0; i < 4; ++i)
                ldm4(ah[i], Abase + a_row + i*2048 + ((kb + a_k) ^ sx));
            #pragma unroll
            for (int p = 0; p < 2; ++p)
                ldm4(bh[p], Bbase + b_row + p*2048 + ((kb + b_k) ^ sx));
            #pragma unroll
            for (int i = 0; i < 4; ++i)
                #pragma unroll
                for (int j = 0; j < 4; ++j)
                    mma16816(acc[i][j], ah[i], &bh[j >> 1][(j & 1) * 2]);
            {
                uint32_t al[4][4];
                #pragma unroll
                for (int i = 0; i < 4; ++i)
                    ldm4(al[i], Abase + a_row + i*2048 + ((64 + kb + a_k) ^ sx));
                #pragma unroll
                for (int i = 0; i < 4; ++i)
                    #pragma unroll
                    for (int j = 0; j < 4; ++j)
                        mma16816(acc[i][j], al[i], &bh[j >> 1][(j & 1) * 2]);
            }
            {
                uint32_t bl[2][4];
                #pragma unroll
                for (int p = 0; p < 2; ++p)
                    ldm4(bl[p], Bbase + b_row + p*2048 + ((64 + kb + b_k) ^ sx));
                #pragma unroll
                for (int i = 0; i < 4; ++i)
                    #pragma unroll
                    for (int j = 0; j < 4; ++j)
                        mma16816(acc[i][j], ah[i], &bl[j >> 1][(j & 1) * 2]);
            }
        }
    }
}

__device__ __forceinline__ void stage_epilogue(char* smem, int tid,
                                               float acc[4][4][4])
{
    __syncthreads();
    float* Cs = (float*)smem;
    const int lane = tid & 31, wid = tid >> 5;
    const int wm = wid >> 2, wn = wid & 3;
    const int frow = wm*64 + (lane >> 2);
    const int fcol = wn*32 + (lane & 3) * 2;
    #pragma unroll
    for (int i = 0; i < 4; ++i)
        #pragma unroll
        for (int j = 0; j < 4; ++j) {
            *(float2*)&Cs[(frow + i*16    )*132 + fcol + j*8] =
                make_float2(acc[i][j][0], acc[i][j][1]);
            *(float2*)&Cs[(frow + i*16 + 8)*132 + fcol + j*8] =
                make_float2(acc[i][j][2], acc[i][j][3]);
        }
    __syncthreads();
}

// ---- fused QKV projection: emits single fp16 (Q prescaled by 1/sqrt(HD)) ----
__global__ void __launch_bounds__(256, 2) gemm_qkv(
    const __nv_bfloat16* __restrict__ Ah, const __nv_bfloat16* __restrict__ Al,
    const __nv_bfloat16* __restrict__ W4h, const __nv_bfloat16* __restrict__ W4l,
    __half* __restrict__ Qf, __half* __restrict__ Kf, __half* __restrict__ Vf,
    const float* __restrict__ cosc, const float* __restrict__ sinc)
{
    extern __shared__ char smem[];
    const uint32_t sb = smem_u32(smem);
    const int tid = threadIdx.x;
    const int m0 = blockIdx.y * 128, n0 = blockIdx.x * 128;
    const int z = blockIdx.z;

    const __nv_bfloat16* Bh = W4h + (size_t)z * WSZ;
    const __nv_bfloat16* Bl = W4l + (size_t)z * WSZ;

    float acc[4][4][4];
    #pragma unroll
    for (int i = 0; i < 4; ++i)
        #pragma unroll
        for (int j = 0; j < 4; ++j)
            #pragma unroll
            for (int q = 0; q < 4; ++q) acc[i][j][q] = 0.f;

    gemm_mainloop(Ah, Al, Bh, Bl, sb, tid, m0, n0, acc);
    stage_epilogue(smem, tid, acc);

    __half* Cf = (z == 0) ? Qf : (z == 1) ? Kf : Vf;
    const bool dorope = (z < 2);
    const float postscale = (z == 0) ? 0.08838834764831845f : 1.0f;

    float* Cs = (float*)smem;
    const int row  = tid >> 1;
    const int half_ = tid & 1;
    const int grow = m0 + row;
    const int h = n0 >> 7;
    int bb = grow >> 11, l = grow & (LL - 1);
    size_t ofs = (((size_t)(bb * NH + h)) * LL + l) * HD;

    #pragma unroll
    for (int c0 = 0; c0 < 32; c0 += 4) {
        const int col = half_*32 + c0;
        float a0[4], a1[4];
        #pragma unroll
        for (int q = 0; q < 4; ++q) {
            a0[q] = Cs[row*132 + col + q];
            a1[q] = Cs[row*132 + col + 64 + q];
        }
        if (dorope) {
            #pragma unroll
            for (int q = 0; q < 4; ++q) {
                float c1 = cosc[h*HD + col + q];
                float s1 = sinc[h*HD + col + q];
                float c2 = cosc[h*HD + col + q + 64];
                float s2 = sinc[h*HD + col + q + 64];
                float v0 = a0[q], v1 = a1[q];
                a0[q] = (v0*c1 - v1*s1) * postscale;
                a1[q] = (v1*c2 + v0*s2) * postscale;
            }
        }
        #pragma unroll
        for (int q = 0; q < 4; q += 2) {
            *(__half2*)(Cf + ofs + col + q)      = __floats2half2_rn(a0[q], a0[q+1]);
            *(__half2*)(Cf + ofs + col + 64 + q) = __floats2half2_rn(a1[q], a1[q+1]);
        }
    }
}

// ---- O-projection: fp32 output ----
__global__ void __launch_bounds__(256, 2) gemm_out(
    const __nv_bfloat16* __restrict__ Ah, const __nv_bfloat16* __restrict__ Al,
    const __nv_bfloat16* __restrict__ Bh, const __nv_bfloat16* __restrict__ Bl,
    float* __restrict__ C)
{
    extern __shared__ char smem[];
    const uint32_t sb = smem_u32(smem);
    const int tid = threadIdx.x;
    const int m0 = blockIdx.y * 128, n0 = blockIdx.x * 128;

    float acc[4][4][4];
    #pragma unroll
    for (int i = 0; i < 4; ++i)
        #pragma unroll
        for (int j = 0; j < 4; ++j)
            #pragma unroll
            for (int q = 0; q < 4; ++q) acc[i][j][q] = 0.f;

    gemm_mainloop(Ah, Al, Bh, Bl, sb, tid, m0, n0, acc);
    stage_epilogue(smem, tid, acc);

    float* Cs = (float*)smem;
    const int row  = tid >> 1;
    const int half_ = tid & 1;
    float* dst = C + (size_t)(m0 + row) * DM + n0;
    #pragma unroll
    for (int c0 = 0; c0 < 32; c0 += 4) {
        const int col = half_*32 + c0;
        *(float4*)(dst + col)      = *(float4*)&Cs[row*132 + col];
        *(float4*)(dst + col + 64) = *(float4*)&Cs[row*132 + col + 64];
    }
}

// ---------------------------------------------------- fp16 flash attention --
// q-tile 64, 256 threads / 8 warps (4 rowg x 2 key-half). Single-product fp16
// (Q prescaled). Double-buffered KV with 2-ahead prefetch -> loads hidden.
// Smem 90KB -> 2 CTAs/SM.
#define APITCH 272
#define AT_KV   17408             /* buf bs at AT_KV + bs*34816: K, V at +17408 */
#define AT_MASK 87040             /* 2048 bytes (uchar) */
#define AT_RED  89088             /* pmax[64][2], psum[64][2] = 1024B */
#define AT_FLAG 90112             /* per-tile all-valid flags, 64B */
#define AT_SMEM 90176

__global__ void __launch_bounds__(256, 2) attn_mma(
    const __half* __restrict__ Qf, const __half* __restrict__ Kf,
    const __half* __restrict__ Vf, const int* __restrict__ mask,
    __nv_bfloat16* __restrict__ Oh, __nv_bfloat16* __restrict__ Ol)
{
    extern __shared__ char sm[];
    const uint32_t sb = smem_u32(sm);
    const int tid = threadIdx.x, lane = tid & 31, wid = tid >> 5;
    const int rowg = wid >> 1;            // 0..3: 16-row group
    const int half = wid & 1;             // key half (32 cols)
    const int q0 = (int)(gridDim.x - 1 - blockIdx.x) * 64;   // heavy first
    const int h = blockIdx.y, b = blockIdx.z;
    const size_t hb = ((size_t)(b*NH + h)) * LL * HD;
    const __half *pQ = Qf + hb, *pK = Kf + hb, *pV = Vf + hb;
    unsigned char* msk = (unsigned char*)(sm + AT_MASK);
    float* pmax = (float*)(sm + AT_RED);      // [64][2]
    float* psum = pmax + 128;                 // [64][2]
    unsigned char* tflag = (unsigned char*)(sm + AT_FLAG);

    for (int i = tid; i < LL; i += 256)
        msk[i] = (unsigned char)(mask[b*LL + i] != 0);

    // Q tile (64 rows x 128 hd, single fp16): 4 cp16 per thread
    {
        int row = tid >> 2;
        int c0 = tid & 3;
        const char* gq = (const char*)(pQ + (size_t)(q0+row)*HD);
        uint32_t dq = sb + row * APITCH;
        #pragma unroll
        for (int t = 0; t < 4; ++t) {
            int c = c0 + 4*t;
            cp16(dq + c*16, gq + c*16);
        }
    }

    auto load_kv = [&](int kt, int bs) {
        int k0 = kt * 64;
        int row = tid >> 2;          // 0..63
        int c0 = tid & 3;
        const char* gk = (const char*)(pK + (size_t)(k0+row)*HD);
        const char* gv = (const char*)(pV + (size_t)(k0+row)*HD);
        uint32_t dk = sb + AT_KV + bs*34816 + row*APITCH;
        uint32_t dv = dk + 17408;
        #pragma unroll
        for (int t = 0; t < 4; ++t) {
            int c = c0 + 4*t;
            cp16(dk + c*16, gk + c*16);
            cp16(dv + c*16, gv + c*16);
        }
        cp_commit();
    };

    const int ntiles = q0/64 + 1;
    load_kv(0, 0);
    load_kv((ntiles > 1) ? 1 : 0, 1);   // harmless prefetch when ntiles==1

    // per-64-key-tile all-valid flags (needs msk complete)
    __syncthreads();
    if (tid < 32) {
        unsigned char f = 1;
        #pragma unroll 8
        for (int j = 0; j < 64; ++j) f &= msk[tid*64 + j];
        tflag[tid] = f;
    }

    float oacc[16][4];
    #pragma unroll
    for (int u = 0; u < 16; ++u)
        #pragma unroll
        for (int q = 0; q < 4; ++q) oacc[u][q] = 0.f;
    float m_i[2] = {-1e30f, -1e30f}, l_i[2] = {0.f, 0.f};

    const uint32_t a_off = sb + (rowg*16 + (lane & 15))*APITCH + (lane >> 4)*16;
    const uint32_t b_off = (uint32_t)((half*32 + ((lane >> 4) & 1)*8 + (lane & 7))*APITCH
                                      + ((lane >> 3) & 1)*16);
    const uint32_t v_off = (uint32_t)((lane & 15)*APITCH + (lane >> 4)*16);
    const int r0 = lane >> 2;
    const int bar_id = rowg + 1;

    for (int kt = 0; kt < ntiles; ++kt) {
        const int bs = kt & 1;
        const int k0 = kt * 64;
        if (kt == ntiles - 1) cp_wait<0>(); else cp_wait<1>();
        __syncthreads();

        const uint32_t kh_base = sb + AT_KV + bs*34816;
        const uint32_t vh_base = kh_base + 17408;

        // ---- S = Q K^T (single fp16 product; Q prescaled) ----
        float sacc[4][4];
        #pragma unroll
        for (int j = 0; j < 4; ++j)
            #pragma unroll
            for (int q = 0; q < 4; ++q) sacc[j][q] = 0.f;

        #pragma unroll 2
        for (int ks = 0; ks < 8; ++ks) {
            const uint32_t ka = ks * 32;
            uint32_t ah[4], bh[2][4];
            ldm4(ah, a_off + ka);
            ldm4(bh[0], kh_base + b_off + ka);
            ldm4(bh[1], kh_base + b_off + 16*APITCH + ka);
            #pragma unroll
            for (int j = 0; j < 4; ++j)
                mma16816h(sacc[j], ah, &bh[j >> 1][(j & 1) * 2]);
        }

        // ---- softmax: (optional) mask + partial max ----
        const bool needmask = (k0 + 64 > q0) || (tflag[kt] == 0);
        #pragma unroll
        for (int rr = 0; rr < 2; ++rr) {
            const int lr = rowg*16 + r0 + rr*8;
            const int qr = q0 + lr;
            float tm = -1e30f;
            if (needmask) {
                #pragma unroll
                for (int j = 0; j < 4; ++j) {
                    #pragma unroll
                    for (int e = 0; e < 2; ++e) {
                        int col = k0 + half*32 + j*8 + (lane & 3)*2 + e;
                        float v = sacc[j][rr*2 + e];
                        if (col > qr || msk[col] == 0) v = -1e15f;
                        sacc[j][rr*2 + e] = v;
                        tm = fmaxf(tm, v);
                    }
                }
            } else {
                #pragma unroll
                for (int j = 0; j < 4; ++j)
                    tm = fmaxf(tm, fmaxf(sacc[j][rr*2], sacc[j][rr*2 + 1]));
            }
            tm = fmaxf(tm, __shfl_xor_sync(0xffffffffu, tm, 1));
            tm = fmaxf(tm, __shfl_xor_sync(0xffffffffu, tm, 2));
            if ((lane & 3) == 0) pmax[lr*2 + half] = tm;
        }
        asm volatile("bar.sync %0, 64;" :: "r"(bar_id) : "memory");

        // ---- combined max, exp, partial sum ----
        float scv[2];
        #pragma unroll
        for (int rr = 0; rr < 2; ++rr) {
            const int lr = rowg*16 + r0 + rr*8;
            float tm = fmaxf(pmax[lr*2], pmax[lr*2 + 1]);
            float mnew = fmaxf(m_i[rr], tm);
            scv[rr] = __expf(m_i[rr] - mnew);
            m_i[rr] = mnew;
            float rs = 0.f;
            #pragma unroll
            for (int j = 0; j < 4; ++j) {
                #pragma unroll
                for (int e = 0; e < 2; ++e) {
                    float p = __expf(sacc[j][rr*2 + e] - mnew);
                    sacc[j][rr*2 + e] = p;
                    rs += p;
                }
            }
            rs += __shfl_xor_sync(0xffffffffu, rs, 1);
            rs += __shfl_xor_sync(0xffffffffu, rs, 2);
            if ((lane & 3) == 0) psum[lr*2 + half] = rs;
            #pragma unroll
            for (int u = 0; u < 16; ++u) {
                oacc[u][rr*2]     *= scv[rr];
                oacc[u][rr*2 + 1] *= scv[rr];
            }
        }
        asm volatile("bar.sync %0, 64;" :: "r"(bar_id) : "memory");

        #pragma unroll
        for (int rr = 0; rr < 2; ++rr) {
            const int lr = rowg*16 + r0 + rr*8;
            l_i[rr] = l_i[rr] * scv[rr] + psum[lr*2] + psum[lr*2 + 1];
        }

        // ---- O += P V over warp's 32 keys (single fp16 product) ----
        #pragma unroll 1
        for (int t = 0; t < 2; ++t) {
            uint32_t pah[4];
            #pragma unroll
            for (int idx = 0; idx < 4; ++idx) {
                int j = 2*t + (idx >> 1);
                int o = (idx & 1) * 2;
                __half2 hv = __floats2half2_rn(sacc[j][o], sacc[j][o + 1]);
                pah[idx] = *(uint32_t*)&hv;
            }
            #pragma unroll
            for (int u = 0; u < 8; ++u) {
                uint32_t vh[4];
                ldm4t(vh, vh_base + (half*32 + t*16)*APITCH + u*32 + v_off);
                mma16816h(oacc[2*u],     pah, vh);
                mma16816h(oacc[2*u + 1], pah, vh + 2);
            }
        }

        __syncthreads();              // all warps done reading buf(bs)
        if (kt + 2 < ntiles) load_kv(kt + 2, bs);
    }

    // ---- combine key-halves via smem (reuse KV buf0), then epilogue ----
    float* Osm = (float*)(sm + AT_KV);      // 64 x 128 fp32 = 32KB
    if (half == 1) {
        #pragma unroll
        for (int rr = 0; rr < 2; ++rr) {
            int r = rowg*16 + r0 + rr*8;
            #pragma unroll
            for (int u = 0; u < 16; ++u) {
                int col = u*8 + (lane & 3)*2;
                Osm[r*128 + col]     = oacc[u][rr*2];
                Osm[r*128 + col + 1] = oacc[u][rr*2 + 1];
            }
        }
    }
    __syncthreads();
    if (half == 0) {
        #pragma unroll
        for (int rr = 0; rr < 2; ++rr) {
            float inv = 1.0f / l_i[rr];
            int r = rowg*16 + r0 + rr*8;
            int lrow = q0 + r;
            size_t base = ((size_t)(b*LL + lrow)) * DM + h*HD;
            #pragma unroll
            for (int u = 0; u < 16; ++u) {
                int col = u*8 + (lane & 3)*2;
                float p0 = (oacc[u][rr*2]     + Osm[r*128 + col])     * inv;
                float p1 = (oacc[u][rr*2 + 1] + Osm[r*128 + col + 1]) * inv;
                __nv_bfloat162 hv = __floats2bfloat162_rn(p0, p1);
                float2 hf = __bfloat1622float2(hv);
                __nv_bfloat162 lv = __floats2bfloat162_rn(p0 - hf.x, p1 - hf.y);
                *(__nv_bfloat162*)(Oh + base + col) = hv;
                *(__nv_bfloat162*)(Ol + base + col) = lv;
            }
        }
    }
}

// ---------------------------------------------------------------------------
extern "C" void kernel_launch(void* const* d_in, const int* in_sizes, int n_in,
                              void* d_out, int out_size)
{
    const float* hidden = (const float*)d_in[0];
    const int*   mask   = (const int*)  d_in[1];
    const float* Wq     = (const float*)d_in[2];
    const float* Wk     = (const float*)d_in[3];
    const float* Wv     = (const float*)d_in[4];
    const float* Wo     = (const float*)d_in[5];
    const float* cosc   = (const float*)d_in[6];
    const float* sinc   = (const float*)d_in[7];
    float* out = (float*)d_out;

    __nv_bfloat16 *Ahp, *Alp, *W4hp, *W4lp;
    __half *Qfp, *Kfp, *Vfp;
    cudaGetSymbolAddress((void**)&Ahp,  g_Ah);
    cudaGetSymbolAddress((void**)&Alp,  g_Al);
    cudaGetSymbolAddress((void**)&W4hp, g_W4h);
    cudaGetSymbolAddress((void**)&W4lp, g_W4l);
    cudaGetSymbolAddress((void**)&Qfp,  g_Qf);
    cudaGetSymbolAddress((void**)&Kfp,  g_Kf);
    cudaGetSymbolAddress((void**)&Vfp,  g_Vf);

    cudaFuncSetAttribute(gemm_qkv, cudaFuncAttributeMaxDynamicSharedMemorySize, GSMEM);
    cudaFuncSetAttribute(gemm_out, cudaFuncAttributeMaxDynamicSharedMemorySize, GSMEM);
    cudaFuncSetAttribute(attn_mma, cudaFuncAttributeMaxDynamicSharedMemorySize, AT_SMEM);

    const int nA4 = MROWS*DM/4, nW4 = DM*DM/4;

    split_kernel<<<(nA4+255)/256, 256>>>(hidden, Ahp, Alp, nA4);
    {
        dim3 gs((nW4+255)/256, 4);
        split4_kernel<<<gs, 256>>>(Wq, Wk, Wv, Wo, W4hp, W4lp, nW4);
    }

    {
        dim3 gg(DM/128, MROWS/128, 3);
        gemm_qkv<<<gg, 256, GSMEM>>>(Ahp, Alp, W4hp, W4lp,
                                     Qfp, Kfp, Vfp, cosc, sinc);
    }

    dim3 ga(LL/64, NH, BB);
    attn_mma<<<ga, 256, AT_SMEM>>>(Qfp, Kfp, Vfp, mask, Ahp, Alp);

    {
        dim3 gg(DM/128, MROWS/128);
        gemm_out<<<gg, 256, GSMEM>>>(Ahp, Alp, W4hp + 3*WSZ, W4lp + 3*WSZ, out);
    }
}

// round 16
// speedup vs baseline: 1.5546x; 1.3148x over previous
#include <cuda_runtime.h>
#include <cuda_bf16.h>
#include <cuda_fp16.h>
#include <cstdint>
#include <math.h>

#define BB 2
#define LL 2048
#define DM 2048
#define NH 16
#define HD 128
#define MROWS (BB*LL)   // 4096
#define WSZ ((size_t)DM*(size_t)DM)

// ---------------------------------------------------------------- scratch ---
__device__ __half g_Ah[MROWS*DM];      // A hi (fp16)
__device__ __half g_Al[MROWS*DM];      // A lo (fp16)
__device__ __half g_W4[4*DM*DM];       // weights, single fp16
__device__ __half g_Qf[MROWS*DM];
__device__ __half g_Kf[MROWS*DM];
__device__ __half g_Vf[MROWS*DM];

// ------------------------------------------------------------ ptx helpers ---
__device__ __forceinline__ uint32_t smem_u32(const void* p) {
    uint32_t a;
    asm("{ .reg .u64 t; cvta.to.shared.u64 t, %1; cvt.u32.u64 %0, t; }"
        : "=r"(a) : "l"(p));
    return a;
}
__device__ __forceinline__ void cp16(uint32_t d, const void* s) {
    asm volatile("cp.async.cg.shared.global [%0], [%1], 16;" :: "r"(d), "l"(s));
}
__device__ __forceinline__ void cp_commit() {
    asm volatile("cp.async.commit_group;" ::: "memory");
}
template<int N> __device__ __forceinline__ void cp_wait() {
    asm volatile("cp.async.wait_group %0;" :: "n"(N) : "memory");
}
__device__ __forceinline__ void ldm4(uint32_t* r, uint32_t addr) {
    asm volatile("ldmatrix.sync.aligned.m8n8.x4.shared.b16 {%0,%1,%2,%3}, [%4];"
                 : "=r"(r[0]), "=r"(r[1]), "=r"(r[2]), "=r"(r[3]) : "r"(addr));
}
__device__ __forceinline__ void ldm4t(uint32_t* r, uint32_t addr) {
    asm volatile("ldmatrix.sync.aligned.m8n8.x4.trans.shared.b16 {%0,%1,%2,%3}, [%4];"
                 : "=r"(r[0]), "=r"(r[1]), "=r"(r[2]), "=r"(r[3]) : "r"(addr));
}
__device__ __forceinline__ void mma16816h(float* c, const uint32_t* a,
                                          const uint32_t* b) {
    asm volatile(
        "mma.sync.aligned.m16n8k16.row.col.f32.f16.f16.f32 "
        "{%0,%1,%2,%3}, {%4,%5,%6,%7}, {%8,%9}, {%0,%1,%2,%3};"
        : "+f"(c[0]), "+f"(c[1]), "+f"(c[2]), "+f"(c[3])
        : "r"(a[0]), "r"(a[1]), "r"(a[2]), "r"(a[3]), "r"(b[0]), "r"(b[1]));
}

// --------------------------------------------------------- fp16 splits -----
__global__ void __launch_bounds__(256) splitA_kernel(
    const float* __restrict__ src, __half* __restrict__ hi,
    __half* __restrict__ lo, int n4)
{
    int i = blockIdx.x * blockDim.x + threadIdx.x;
    if (i >= n4) return;
    float4 a = ((const float4*)src)[i];
    __half h0 = __float2half_rn(a.x);
    __half h1 = __float2half_rn(a.y);
    __half h2 = __float2half_rn(a.z);
    __half h3 = __float2half_rn(a.w);
    __half l0 = __float2half_rn(a.x - __half2float(h0));
    __half l1 = __float2half_rn(a.y - __half2float(h1));
    __half l2 = __float2half_rn(a.z - __half2float(h2));
    __half l3 = __float2half_rn(a.w - __half2float(h3));
    ((__half2*)hi)[2*i]   = __half2(h0, h1);
    ((__half2*)hi)[2*i+1] = __half2(h2, h3);
    ((__half2*)lo)[2*i]   = __half2(l0, l1);
    ((__half2*)lo)[2*i+1] = __half2(l2, l3);
}

// all four weights -> single fp16, slot w at offset w*WSZ
__global__ void __launch_bounds__(256) cvtW_kernel(
    const float* __restrict__ s0, const float* __restrict__ s1,
    const float* __restrict__ s2, const float* __restrict__ s3,
    __half* __restrict__ dst, int n4)
{
    int i = blockIdx.x * blockDim.x + threadIdx.x;
    if (i >= n4) return;
    int w = blockIdx.y;
    const float* src = (w == 0) ? s0 : (w == 1) ? s1 : (w == 2) ? s2 : s3;
    float4 a = ((const float4*)src)[i];
    __half* d = dst + (size_t)w * WSZ;
    ((__half2*)d)[2*i]   = __floats2half2_rn(a.x, a.y);
    ((__half2*)d)[2*i+1] = __floats2half2_rn(a.z, a.w);
}

// ------------------------------------------- fp16 GEMM (A=Ah+Al, W single) --
// A rows packed [hi(64B)|lo(64B)] = 128B; B occupies hi-half only.
// Stage 32KB, 3 stages = 96KB -> 2 CTAs/SM. Per kk: 10 LDSM, 32 HMMA.
#define AREG  16384
#define STGB  32768
#define GSTG  3
#define GSMEM (GSTG*STGB)     /* 98304 */

__device__ __forceinline__ void gemm_mainloop(
    const __half* __restrict__ Ah, const __half* __restrict__ Al,
    const __half* __restrict__ B,
    uint32_t sb, int tid, int m0, int n0, float acc[4][4][4])
{
    const int lane = tid & 31, wid = tid >> 5;
    const int wm = wid >> 2, wn = wid & 3;
    const int S = DM / 32;

    const int lr = tid >> 1;
    const uint32_t lsx = (uint32_t)(lr & 7) << 4;
    const int lj0 = (tid & 1) * 2;
    const size_t ga = (size_t)(m0 + lr) * DM;
    const size_t gb = (size_t)(n0 + lr) * DM;

    auto load_stage = [&](int s) {
        const int k0 = s * 32;
        const uint32_t ab = sb + (s % GSTG) * STGB + (uint32_t)lr * 128;
        const uint32_t bbs = ab + AREG;
        const char* pah = (const char*)(Ah + ga + k0);
        const char* pal = (const char*)(Al + ga + k0);
        const char* pb  = (const char*)(B  + gb + k0);
        #pragma unroll
        for (int q = 0; q < 2; ++q) {
            const int j = lj0 + q;
            cp16(ab  + (((uint32_t)(j    ) << 4) ^ lsx), pah + j*16);
            cp16(ab  + (((uint32_t)(j + 4) << 4) ^ lsx), pal + j*16);
            cp16(bbs + (((uint32_t)(j    ) << 4) ^ lsx), pb  + j*16);
        }
        cp_commit();
    };

    load_stage(0);
    load_stage(1);

    const uint32_t sx = (uint32_t)(lane & 7) << 4;
    const uint32_t a_row = (uint32_t)(wm*64 + (lane & 15)) * 128;
    const uint32_t a_k   = (uint32_t)(lane >> 4) << 4;
    const uint32_t b_row = (uint32_t)(wn*32 + ((lane >> 4) & 1)*8 + (lane & 7)) * 128;
    const uint32_t b_k   = (uint32_t)((lane >> 3) & 1) << 4;

    for (int s = 0; s < S; ++s) {
        if (s == S - 1) cp_wait<0>(); else cp_wait<1>();
        __syncthreads();
        if (s + 2 < S) load_stage(s + 2);

        const uint32_t Abase = sb + (s % GSTG) * STGB;
        const uint32_t Bbase = Abase + AREG;
        #pragma unroll
        for (int kk = 0; kk < 2; ++kk) {
            const uint32_t kb = (uint32_t)kk * 32;
            uint32_t ah[4][4], bh[2][4];
            #pragma unroll
            for (int i = 0; i < 4; ++i)
                ldm4(ah[i], Abase + a_row + i*2048 + ((kb + a_k) ^ sx));
            #pragma unroll
            for (int p = 0; p < 2; ++p)
                ldm4(bh[p], Bbase + b_row + p*2048 + ((kb + b_k) ^ sx));
            #pragma unroll
            for (int i = 0; i < 4; ++i)
                #pragma unroll
                for (int j = 0; j < 4; ++j)
                    mma16816h(acc[i][j], ah[i], &bh[j >> 1][(j & 1) * 2]);
            {
                uint32_t al[4][4];
                #pragma unroll
                for (int i = 0; i < 4; ++i)
                    ldm4(al[i], Abase + a_row + i*2048 + ((64 + kb + a_k) ^ sx));
                #pragma unroll
                for (int i = 0; i < 4; ++i)
                    #pragma unroll
                    for (int j = 0; j < 4; ++j)
                        mma16816h(acc[i][j], al[i], &bh[j >> 1][(j & 1) * 2]);
            }
        }
    }
}

__device__ __forceinline__ void stage_epilogue(char* smem, int tid,
                                               float acc[4][4][4])
{
    __syncthreads();
    float* Cs = (float*)smem;
    const int lane = tid & 31, wid = tid >> 5;
    const int wm = wid >> 2, wn = wid & 3;
    const int frow = wm*64 + (lane >> 2);
    const int fcol = wn*32 + (lane & 3) * 2;
    #pragma unroll
    for (int i = 0; i < 4; ++i)
        #pragma unroll
        for (int j = 0; j < 4; ++j) {
            *(float2*)&Cs[(frow + i*16    )*132 + fcol + j*8] =
                make_float2(acc[i][j][0], acc[i][j][1]);
            *(float2*)&Cs[(frow + i*16 + 8)*132 + fcol + j*8] =
                make_float2(acc[i][j][2], acc[i][j][3]);
        }
    __syncthreads();
}

// ---- fused QKV projection: emits single fp16 (Q prescaled by 1/sqrt(HD)) ----
__global__ void __launch_bounds__(256, 2) gemm_qkv(
    const __half* __restrict__ Ah, const __half* __restrict__ Al,
    const __half* __restrict__ W4,
    __half* __restrict__ Qf, __half* __restrict__ Kf, __half* __restrict__ Vf,
    const float* __restrict__ cosc, const float* __restrict__ sinc)
{
    extern __shared__ char smem[];
    const uint32_t sb = smem_u32(smem);
    const int tid = threadIdx.x;
    const int m0 = blockIdx.y * 128, n0 = blockIdx.x * 128;
    const int z = blockIdx.z;

    const __half* B = W4 + (size_t)z * WSZ;

    float acc[4][4][4];
    #pragma unroll
    for (int i = 0; i < 4; ++i)
        #pragma unroll
        for (int j = 0; j < 4; ++j)
            #pragma unroll
            for (int q = 0; q < 4; ++q) acc[i][j][q] = 0.f;

    gemm_mainloop(Ah, Al, B, sb, tid, m0, n0, acc);
    stage_epilogue(smem, tid, acc);

    __half* Cf = (z == 0) ? Qf : (z == 1) ? Kf : Vf;
    const bool dorope = (z < 2);
    const float postscale = (z == 0) ? 0.08838834764831845f : 1.0f;

    float* Cs = (float*)smem;
    const int row  = tid >> 1;
    const int half_ = tid & 1;
    const int grow = m0 + row;
    const int h = n0 >> 7;
    int bb = grow >> 11, l = grow & (LL - 1);
    size_t ofs = (((size_t)(bb * NH + h)) * LL + l) * HD;

    #pragma unroll
    for (int c0 = 0; c0 < 32; c0 += 4) {
        const int col = half_*32 + c0;
        float a0[4], a1[4];
        #pragma unroll
        for (int q = 0; q < 4; ++q) {
            a0[q] = Cs[row*132 + col + q];
            a1[q] = Cs[row*132 + col + 64 + q];
        }
        if (dorope) {
            #pragma unroll
            for (int q = 0; q < 4; ++q) {
                float c1 = cosc[h*HD + col + q];
                float s1 = sinc[h*HD + col + q];
                float c2 = cosc[h*HD + col + q + 64];
                float s2 = sinc[h*HD + col + q + 64];
                float v0 = a0[q], v1 = a1[q];
                a0[q] = (v0*c1 - v1*s1) * postscale;
                a1[q] = (v1*c2 + v0*s2) * postscale;
            }
        }
        #pragma unroll
        for (int q = 0; q < 4; q += 2) {
            *(__half2*)(Cf + ofs + col + q)      = __floats2half2_rn(a0[q], a0[q+1]);
            *(__half2*)(Cf + ofs + col + 64 + q) = __floats2half2_rn(a1[q], a1[q+1]);
        }
    }
}

// ---- O-projection: fp32 output ----
__global__ void __launch_bounds__(256, 2) gemm_out(
    const __half* __restrict__ Ah, const __half* __restrict__ Al,
    const __half* __restrict__ B, float* __restrict__ C)
{
    extern __shared__ char smem[];
    const uint32_t sb = smem_u32(smem);
    const int tid = threadIdx.x;
    const int m0 = blockIdx.y * 128, n0 = blockIdx.x * 128;

    float acc[4][4][4];
    #pragma unroll
    for (int i = 0; i < 4; ++i)
        #pragma unroll
        for (int j = 0; j < 4; ++j)
            #pragma unroll
            for (int q = 0; q < 4; ++q) acc[i][j][q] = 0.f;

    gemm_mainloop(Ah, Al, B, sb, tid, m0, n0, acc);
    stage_epilogue(smem, tid, acc);

    float* Cs = (float*)smem;
    const int row  = tid >> 1;
    const int half_ = tid & 1;
    float* dst = C + (size_t)(m0 + row) * DM + n0;
    #pragma unroll
    for (int c0 = 0; c0 < 32; c0 += 4) {
        const int col = half_*32 + c0;
        *(float4*)(dst + col)      = *(float4*)&Cs[row*132 + col];
        *(float4*)(dst + col + 64) = *(float4*)&Cs[row*132 + col + 64];
    }
}

// ---------------------------------------------------- fp16 flash attention --
// q-tile 64, 256 threads / 8 warps (4 rowg x 2 key-half). Single-product fp16
// (Q prescaled). Double-buffered KV, 2-ahead prefetch. 90KB -> 2 CTAs/SM.
#define APITCH 272
#define AT_KV   17408             /* buf bs at AT_KV + bs*34816: K, V at +17408 */
#define AT_MASK 87040             /* 2048 bytes (uchar) */
#define AT_RED  89088             /* pmax[64][2], psum[64][2] = 1024B */
#define AT_FLAG 90112             /* per-tile all-valid flags, 64B */
#define AT_SMEM 90176

__global__ void __launch_bounds__(256, 2) attn_mma(
    const __half* __restrict__ Qf, const __half* __restrict__ Kf,
    const __half* __restrict__ Vf, const int* __restrict__ mask,
    __half* __restrict__ Oh, __half* __restrict__ Ol)
{
    extern __shared__ char sm[];
    const uint32_t sb = smem_u32(sm);
    const int tid = threadIdx.x, lane = tid & 31, wid = tid >> 5;
    const int rowg = wid >> 1;            // 0..3: 16-row group
    const int half = wid & 1;             // key half (32 cols)
    const int q0 = (int)(gridDim.x - 1 - blockIdx.x) * 64;   // heavy first
    const int h = blockIdx.y, b = blockIdx.z;
    const size_t hb = ((size_t)(b*NH + h)) * LL * HD;
    const __half *pQ = Qf + hb, *pK = Kf + hb, *pV = Vf + hb;
    unsigned char* msk = (unsigned char*)(sm + AT_MASK);
    float* pmax = (float*)(sm + AT_RED);      // [64][2]
    float* psum = pmax + 128;                 // [64][2]
    unsigned char* tflag = (unsigned char*)(sm + AT_FLAG);

    for (int i = tid; i < LL; i += 256)
        msk[i] = (unsigned char)(mask[b*LL + i] != 0);

    // Q tile (64 rows x 128 hd, single fp16): 4 cp16 per thread
    {
        int row = tid >> 2;
        int c0 = tid & 3;
        const char* gq = (const char*)(pQ + (size_t)(q0+row)*HD);
        uint32_t dq = sb + row * APITCH;
        #pragma unroll
        for (int t = 0; t < 4; ++t) {
            int c = c0 + 4*t;
            cp16(dq + c*16, gq + c*16);
        }
    }

    auto load_kv = [&](int kt, int bs) {
        int k0 = kt * 64;
        int row = tid >> 2;          // 0..63
        int c0 = tid & 3;
        const char* gk = (const char*)(pK + (size_t)(k0+row)*HD);
        const char* gv = (const char*)(pV + (size_t)(k0+row)*HD);
        uint32_t dk = sb + AT_KV + bs*34816 + row*APITCH;
        uint32_t dv = dk + 17408;
        #pragma unroll
        for (int t = 0; t < 4; ++t) {
            int c = c0 + 4*t;
            cp16(dk + c*16, gk + c*16);
            cp16(dv + c*16, gv + c*16);
        }
        cp_commit();
    };

    const int ntiles = q0/64 + 1;
    load_kv(0, 0);
    load_kv((ntiles > 1) ? 1 : 0, 1);   // harmless prefetch when ntiles==1

    __syncthreads();
    if (tid < 32) {
        unsigned char f = 1;
        #pragma unroll 8
        for (int j = 0; j < 64; ++j) f &= msk[tid*64 + j];
        tflag[tid] = f;
    }

    float oacc[16][4];
    #pragma unroll
    for (int u = 0; u < 16; ++u)
        #pragma unroll
        for (int q = 0; q < 4; ++q) oacc[u][q] = 0.f;
    float m_i[2] = {-1e30f, -1e30f}, l_i[2] = {0.f, 0.f};

    const uint32_t a_off = sb + (rowg*16 + (lane & 15))*APITCH + (lane >> 4)*16;
    const uint32_t b_off = (uint32_t)((half*32 + ((lane >> 4) & 1)*8 + (lane & 7))*APITCH
                                      + ((lane >> 3) & 1)*16);
    const uint32_t v_off = (uint32_t)((lane & 15)*APITCH + (lane >> 4)*16);
    const int r0 = lane >> 2;
    const int bar_id = rowg + 1;

    for (int kt = 0; kt < ntiles; ++kt) {
        const int bs = kt & 1;
        const int k0 = kt * 64;
        if (kt == ntiles - 1) cp_wait<0>(); else cp_wait<1>();
        __syncthreads();

        const uint32_t kh_base = sb + AT_KV + bs*34816;
        const uint32_t vh_base = kh_base + 17408;

        // ---- S = Q K^T (single fp16 product; Q prescaled) ----
        float sacc[4][4];
        #pragma unroll
        for (int j = 0; j < 4; ++j)
            #pragma unroll
            for (int q = 0; q < 4; ++q) sacc[j][q] = 0.f;

        #pragma unroll 2
        for (int ks = 0; ks < 8; ++ks) {
            const uint32_t ka = ks * 32;
            uint32_t ah[4], bh[2][4];
            ldm4(ah, a_off + ka);
            ldm4(bh[0], kh_base + b_off + ka);
            ldm4(bh[1], kh_base + b_off + 16*APITCH + ka);
            #pragma unroll
            for (int j = 0; j < 4; ++j)
                mma16816h(sacc[j], ah, &bh[j >> 1][(j & 1) * 2]);
        }

        // ---- softmax: (optional) mask + partial max ----
        const bool needmask = (k0 + 64 > q0) || (tflag[kt] == 0);
        #pragma unroll
        for (int rr = 0; rr < 2; ++rr) {
            const int lr = rowg*16 + r0 + rr*8;
            const int qr = q0 + lr;
            float tm = -1e30f;
            if (needmask) {
                #pragma unroll
                for (int j = 0; j < 4; ++j) {
                    #pragma unroll
                    for (int e = 0; e < 2; ++e) {
                        int col = k0 + half*32 + j*8 + (lane & 3)*2 + e;
                        float v = sacc[j][rr*2 + e];
                        if (col > qr || msk[col] == 0) v = -1e15f;
                        sacc[j][rr*2 + e] = v;
                        tm = fmaxf(tm, v);
                    }
                }
            } else {
                #pragma unroll
                for (int j = 0; j < 4; ++j)
                    tm = fmaxf(tm, fmaxf(sacc[j][rr*2], sacc[j][rr*2 + 1]));
            }
            tm = fmaxf(tm, __shfl_xor_sync(0xffffffffu, tm, 1));
            tm = fmaxf(tm, __shfl_xor_sync(0xffffffffu, tm, 2));
            if ((lane & 3) == 0) pmax[lr*2 + half] = tm;
        }
        asm volatile("bar.sync %0, 64;" :: "r"(bar_id) : "memory");

        // ---- combined max, exp, partial sum ----
        float scv[2];
        #pragma unroll
        for (int rr = 0; rr < 2; ++rr) {
            const int lr = rowg*16 + r0 + rr*8;
            float tm = fmaxf(pmax[lr*2], pmax[lr*2 + 1]);
            float mnew = fmaxf(m_i[rr], tm);
            scv[rr] = __expf(m_i[rr] - mnew);
            m_i[rr] = mnew;
            float rs = 0.f;
            #pragma unroll
            for (int j = 0; j < 4; ++j) {
                #pragma unroll
                for (int e = 0; e < 2; ++e) {
                    float p = __expf(sacc[j][rr*2 + e] - mnew);
                    sacc[j][rr*2 + e] = p;
                    rs += p;
                }
            }
            rs += __shfl_xor_sync(0xffffffffu, rs, 1);
            rs += __shfl_xor_sync(0xffffffffu, rs, 2);
            if ((lane & 3) == 0) psum[lr*2 + half] = rs;
            #pragma unroll
            for (int u = 0; u < 16; ++u) {
                oacc[u][rr*2]     *= scv[rr];
                oacc[u][rr*2 + 1] *= scv[rr];
            }
        }
        asm volatile("bar.sync %0, 64;" :: "r"(bar_id) : "memory");

        #pragma unroll
        for (int rr = 0; rr < 2; ++rr) {
            const int lr = rowg*16 + r0 + rr*8;
            l_i[rr] = l_i[rr] * scv[rr] + psum[lr*2] + psum[lr*2 + 1];
        }

        // ---- O += P V over warp's 32 keys (single fp16 product) ----
        #pragma unroll 1
        for (int t = 0; t < 2; ++t) {
            uint32_t pah[4];
            #pragma unroll
            for (int idx = 0; idx < 4; ++idx) {
                int j = 2*t + (idx >> 1);
                int o = (idx & 1) * 2;
                __half2 hv = __floats2half2_rn(sacc[j][o], sacc[j][o + 1]);
                pah[idx] = *(uint32_t*)&hv;
            }
            #pragma unroll
            for (int u = 0; u < 8; ++u) {
                uint32_t vh[4];
                ldm4t(vh, vh_base + (half*32 + t*16)*APITCH + u*32 + v_off);
                mma16816h(oacc[2*u],     pah, vh);
                mma16816h(oacc[2*u + 1], pah, vh + 2);
            }
        }

        __syncthreads();              // all warps done reading buf(bs)
        if (kt + 2 < ntiles) load_kv(kt + 2, bs);
    }

    // ---- combine key-halves via smem (reuse KV buf0), then epilogue ----
    float* Osm = (float*)(sm + AT_KV);      // 64 x 128 fp32 = 32KB
    if (half == 1) {
        #pragma unroll
        for (int rr = 0; rr < 2; ++rr) {
            int r = rowg*16 + r0 + rr*8;
            #pragma unroll
            for (int u = 0; u < 16; ++u) {
                int col = u*8 + (lane & 3)*2;
                Osm[r*128 + col]     = oacc[u][rr*2];
                Osm[r*128 + col + 1] = oacc[u][rr*2 + 1];
            }
        }
    }
    __syncthreads();
    if (half == 0) {
        #pragma unroll
        for (int rr = 0; rr < 2; ++rr) {
            float inv = 1.0f / l_i[rr];
            int r = rowg*16 + r0 + rr*8;
            int lrow = q0 + r;
            size_t base = ((size_t)(b*LL + lrow)) * DM + h*HD;
            #pragma unroll
            for (int u = 0; u < 16; ++u) {
                int col = u*8 + (lane & 3)*2;
                float p0 = (oacc[u][rr*2]     + Osm[r*128 + col])     * inv;
                float p1 = (oacc[u][rr*2 + 1] + Osm[r*128 + col + 1]) * inv;
                __half2 hv = __floats2half2_rn(p0, p1);
                float2 hf = __half22float2(hv);
                __half2 lv = __floats2half2_rn(p0 - hf.x, p1 - hf.y);
                *(__half2*)(Oh + base + col) = hv;
                *(__half2*)(Ol + base + col) = lv;
            }
        }
    }
}

// ---------------------------------------------------------------------------
extern "C" void kernel_launch(void* const* d_in, const int* in_sizes, int n_in,
                              void* d_out, int out_size)
{
    const float* hidden = (const float*)d_in[0];
    const int*   mask   = (const int*)  d_in[1];
    const float* Wq     = (const float*)d_in[2];
    const float* Wk     = (const float*)d_in[3];
    const float* Wv     = (const float*)d_in[4];
    const float* Wo     = (const float*)d_in[5];
    const float* cosc   = (const float*)d_in[6];
    const float* sinc   = (const float*)d_in[7];
    float* out = (float*)d_out;

    __half *Ahp, *Alp, *W4p, *Qfp, *Kfp, *Vfp;
    cudaGetSymbolAddress((void**)&Ahp, g_Ah);
    cudaGetSymbolAddress((void**)&Alp, g_Al);
    cudaGetSymbolAddress((void**)&W4p, g_W4);
    cudaGetSymbolAddress((void**)&Qfp, g_Qf);
    cudaGetSymbolAddress((void**)&Kfp, g_Kf);
    cudaGetSymbolAddress((void**)&Vfp, g_Vf);

    cudaFuncSetAttribute(gemm_qkv, cudaFuncAttributeMaxDynamicSharedMemorySize, GSMEM);
    cudaFuncSetAttribute(gemm_out, cudaFuncAttributeMaxDynamicSharedMemorySize, GSMEM);
    cudaFuncSetAttribute(attn_mma, cudaFuncAttributeMaxDynamicSharedMemorySize, AT_SMEM);

    const int nA4 = MROWS*DM/4, nW4 = DM*DM/4;

    splitA_kernel<<<(nA4+255)/256, 256>>>(hidden, Ahp, Alp, nA4);
    {
        dim3 gs((nW4+255)/256, 4);
        cvtW_kernel<<<gs, 256>>>(Wq, Wk, Wv, Wo, W4p, nW4);
    }

    {
        dim3 gg(DM/128, MROWS/128, 3);
        gemm_qkv<<<gg, 256, GSMEM>>>(Ahp, Alp, W4p, Qfp, Kfp, Vfp, cosc, sinc);
    }

    dim3 ga(LL/64, NH, BB);
    attn_mma<<<ga, 256, AT_SMEM>>>(Qfp, Kfp, Vfp, mask, Ahp, Alp);

    {
        dim3 gg(DM/128, MROWS/128);
        gemm_out<<<gg, 256, GSMEM>>>(Ahp, Alp, W4p + 3*WSZ, out);
    }
}

// round 17
// speedup vs baseline: 1.9748x; 1.2703x over previous
#include <cuda_runtime.h>
#include <cuda_bf16.h>
#include <cuda_fp16.h>
#include <cstdint>
#include <math.h>

#define BB 2
#define LL 2048
#define DM 2048
#define NH 16
#define HD 128
#define MROWS (BB*LL)   // 4096
#define WSZ ((size_t)DM*(size_t)DM)

// ---------------------------------------------------------------- scratch ---
__device__ __half g_Ah[MROWS*DM];      // hidden fp16, later attn-out hi
__device__ __half g_Al[MROWS*DM];      // attn-out lo
__device__ __half g_W4[4*DM*DM];       // weights, single fp16
__device__ __half g_Qf[MROWS*DM];
__device__ __half g_Kf[MROWS*DM];
__device__ __half g_Vf[MROWS*DM];

// ------------------------------------------------------------ ptx helpers ---
__device__ __forceinline__ uint32_t smem_u32(const void* p) {
    uint32_t a;
    asm("{ .reg .u64 t; cvta.to.shared.u64 t, %1; cvt.u32.u64 %0, t; }"
        : "=r"(a) : "l"(p));
    return a;
}
__device__ __forceinline__ void cp16(uint32_t d, const void* s) {
    asm volatile("cp.async.cg.shared.global [%0], [%1], 16;" :: "r"(d), "l"(s));
}
__device__ __forceinline__ void cp_commit() {
    asm volatile("cp.async.commit_group;" ::: "memory");
}
template<int N> __device__ __forceinline__ void cp_wait() {
    asm volatile("cp.async.wait_group %0;" :: "n"(N) : "memory");
}
__device__ __forceinline__ void ldm4(uint32_t* r, uint32_t addr) {
    asm volatile("ldmatrix.sync.aligned.m8n8.x4.shared.b16 {%0,%1,%2,%3}, [%4];"
                 : "=r"(r[0]), "=r"(r[1]), "=r"(r[2]), "=r"(r[3]) : "r"(addr));
}
__device__ __forceinline__ void ldm4t(uint32_t* r, uint32_t addr) {
    asm volatile("ldmatrix.sync.aligned.m8n8.x4.trans.shared.b16 {%0,%1,%2,%3}, [%4];"
                 : "=r"(r[0]), "=r"(r[1]), "=r"(r[2]), "=r"(r[3]) : "r"(addr));
}
__device__ __forceinline__ void mma16816h(float* c, const uint32_t* a,
                                          const uint32_t* b) {
    asm volatile(
        "mma.sync.aligned.m16n8k16.row.col.f32.f16.f16.f32 "
        "{%0,%1,%2,%3}, {%4,%5,%6,%7}, {%8,%9}, {%0,%1,%2,%3};"
        : "+f"(c[0]), "+f"(c[1]), "+f"(c[2]), "+f"(c[3])
        : "r"(a[0]), "r"(a[1]), "r"(a[2]), "r"(a[3]), "r"(b[0]), "r"(b[1]));
}

// --------------------------------------------------------- fp16 converts ---
__global__ void __launch_bounds__(256) cvt1_kernel(
    const float* __restrict__ src, __half* __restrict__ dst, int n4)
{
    int i = blockIdx.x * blockDim.x + threadIdx.x;
    if (i >= n4) return;
    float4 a = ((const float4*)src)[i];
    ((__half2*)dst)[2*i]   = __floats2half2_rn(a.x, a.y);
    ((__half2*)dst)[2*i+1] = __floats2half2_rn(a.z, a.w);
}

// all four weights -> single fp16, slot w at offset w*WSZ
__global__ void __launch_bounds__(256) cvtW_kernel(
    const float* __restrict__ s0, const float* __restrict__ s1,
    const float* __restrict__ s2, const float* __restrict__ s3,
    __half* __restrict__ dst, int n4)
{
    int i = blockIdx.x * blockDim.x + threadIdx.x;
    if (i >= n4) return;
    int w = blockIdx.y;
    const float* src = (w == 0) ? s0 : (w == 1) ? s1 : (w == 2) ? s2 : s3;
    float4 a = ((const float4*)src)[i];
    __half* d = dst + (size_t)w * WSZ;
    ((__half2*)d)[2*i]   = __floats2half2_rn(a.x, a.y);
    ((__half2*)d)[2*i+1] = __floats2half2_rn(a.z, a.w);
}

// ------------------------------------------------------------- fp16 GEMM ---
// NP=1: C = A*W^T (single product).  NP=2: C = (Ah+Al)*W^T.
// A rows packed [hi(64B)|lo(64B)] = 128B; B occupies hi-half only.
#define AREG  16384
#define STGB  32768
#define GSTG  3
#define GSMEM (GSTG*STGB)     /* 98304 */

template<int NP>
__device__ __forceinline__ void gemm_mainloop(
    const __half* __restrict__ Ah, const __half* __restrict__ Al,
    const __half* __restrict__ B,
    uint32_t sb, int tid, int m0, int n0, float acc[4][4][4])
{
    const int lane = tid & 31, wid = tid >> 5;
    const int wm = wid >> 2, wn = wid & 3;
    const int S = DM / 32;

    const int lr = tid >> 1;
    const uint32_t lsx = (uint32_t)(lr & 7) << 4;
    const int lj0 = (tid & 1) * 2;
    const size_t ga = (size_t)(m0 + lr) * DM;
    const size_t gb = (size_t)(n0 + lr) * DM;

    auto load_stage = [&](int s) {
        const int k0 = s * 32;
        const uint32_t ab = sb + (s % GSTG) * STGB + (uint32_t)lr * 128;
        const uint32_t bbs = ab + AREG;
        const char* pah = (const char*)(Ah + ga + k0);
        const char* pal = (const char*)(Al + ga + k0);
        const char* pb  = (const char*)(B  + gb + k0);
        #pragma unroll
        for (int q = 0; q < 2; ++q) {
            const int j = lj0 + q;
            cp16(ab  + (((uint32_t)(j    ) << 4) ^ lsx), pah + j*16);
            if (NP == 2)
                cp16(ab + (((uint32_t)(j + 4) << 4) ^ lsx), pal + j*16);
            cp16(bbs + (((uint32_t)(j    ) << 4) ^ lsx), pb  + j*16);
        }
        cp_commit();
    };

    load_stage(0);
    load_stage(1);

    const uint32_t sx = (uint32_t)(lane & 7) << 4;
    const uint32_t a_row = (uint32_t)(wm*64 + (lane & 15)) * 128;
    const uint32_t a_k   = (uint32_t)(lane >> 4) << 4;
    const uint32_t b_row = (uint32_t)(wn*32 + ((lane >> 4) & 1)*8 + (lane & 7)) * 128;
    const uint32_t b_k   = (uint32_t)((lane >> 3) & 1) << 4;

    for (int s = 0; s < S; ++s) {
        if (s == S - 1) cp_wait<0>(); else cp_wait<1>();
        __syncthreads();
        if (s + 2 < S) load_stage(s + 2);

        const uint32_t Abase = sb + (s % GSTG) * STGB;
        const uint32_t Bbase = Abase + AREG;
        #pragma unroll
        for (int kk = 0; kk < 2; ++kk) {
            const uint32_t kb = (uint32_t)kk * 32;
            uint32_t ah[4][4], bh[2][4];
            #pragma unroll
            for (int i = 0; i < 4; ++i)
                ldm4(ah[i], Abase + a_row + i*2048 + ((kb + a_k) ^ sx));
            #pragma unroll
            for (int p = 0; p < 2; ++p)
                ldm4(bh[p], Bbase + b_row + p*2048 + ((kb + b_k) ^ sx));
            #pragma unroll
            for (int i = 0; i < 4; ++i)
                #pragma unroll
                for (int j = 0; j < 4; ++j)
                    mma16816h(acc[i][j], ah[i], &bh[j >> 1][(j & 1) * 2]);
            if (NP == 2) {
                uint32_t al[4][4];
                #pragma unroll
                for (int i = 0; i < 4; ++i)
                    ldm4(al[i], Abase + a_row + i*2048 + ((64 + kb + a_k) ^ sx));
                #pragma unroll
                for (int i = 0; i < 4; ++i)
                    #pragma unroll
                    for (int j = 0; j < 4; ++j)
                        mma16816h(acc[i][j], al[i], &bh[j >> 1][(j & 1) * 2]);
            }
        }
    }
}

__device__ __forceinline__ void stage_epilogue(char* smem, int tid,
                                               float acc[4][4][4])
{
    __syncthreads();
    float* Cs = (float*)smem;
    const int lane = tid & 31, wid = tid >> 5;
    const int wm = wid >> 2, wn = wid & 3;
    const int frow = wm*64 + (lane >> 2);
    const int fcol = wn*32 + (lane & 3) * 2;
    #pragma unroll
    for (int i = 0; i < 4; ++i)
        #pragma unroll
        for (int j = 0; j < 4; ++j) {
            *(float2*)&Cs[(frow + i*16    )*132 + fcol + j*8] =
                make_float2(acc[i][j][0], acc[i][j][1]);
            *(float2*)&Cs[(frow + i*16 + 8)*132 + fcol + j*8] =
                make_float2(acc[i][j][2], acc[i][j][3]);
        }
    __syncthreads();
}

// ---- fused QKV projection (single-product A): emits fp16, Q prescaled ----
__global__ void __launch_bounds__(256, 2) gemm_qkv(
    const __half* __restrict__ Af, const __half* __restrict__ W4,
    __half* __restrict__ Qf, __half* __restrict__ Kf, __half* __restrict__ Vf,
    const float* __restrict__ cosc, const float* __restrict__ sinc)
{
    extern __shared__ char smem[];
    const uint32_t sb = smem_u32(smem);
    const int tid = threadIdx.x;
    const int m0 = blockIdx.y * 128, n0 = blockIdx.x * 128;
    const int z = blockIdx.z;

    const __half* B = W4 + (size_t)z * WSZ;

    float acc[4][4][4];
    #pragma unroll
    for (int i = 0; i < 4; ++i)
        #pragma unroll
        for (int j = 0; j < 4; ++j)
            #pragma unroll
            for (int q = 0; q < 4; ++q) acc[i][j][q] = 0.f;

    gemm_mainloop<1>(Af, Af, B, sb, tid, m0, n0, acc);
    stage_epilogue(smem, tid, acc);

    __half* Cf = (z == 0) ? Qf : (z == 1) ? Kf : Vf;
    const bool dorope = (z < 2);
    const float postscale = (z == 0) ? 0.08838834764831845f : 1.0f;

    float* Cs = (float*)smem;
    const int row  = tid >> 1;
    const int half_ = tid & 1;
    const int grow = m0 + row;
    const int h = n0 >> 7;
    int bb = grow >> 11, l = grow & (LL - 1);
    size_t ofs = (((size_t)(bb * NH + h)) * LL + l) * HD;

    #pragma unroll
    for (int c0 = 0; c0 < 32; c0 += 4) {
        const int col = half_*32 + c0;
        float a0[4], a1[4];
        #pragma unroll
        for (int q = 0; q < 4; ++q) {
            a0[q] = Cs[row*132 + col + q];
            a1[q] = Cs[row*132 + col + 64 + q];
        }
        if (dorope) {
            #pragma unroll
            for (int q = 0; q < 4; ++q) {
                float c1 = cosc[h*HD + col + q];
                float s1 = sinc[h*HD + col + q];
                float c2 = cosc[h*HD + col + q + 64];
                float s2 = sinc[h*HD + col + q + 64];
                float v0 = a0[q], v1 = a1[q];
                a0[q] = (v0*c1 - v1*s1) * postscale;
                a1[q] = (v1*c2 + v0*s2) * postscale;
            }
        }
        #pragma unroll
        for (int q = 0; q < 4; q += 2) {
            *(__half2*)(Cf + ofs + col + q)      = __floats2half2_rn(a0[q], a0[q+1]);
            *(__half2*)(Cf + ofs + col + 64 + q) = __floats2half2_rn(a1[q], a1[q+1]);
        }
    }
}

// ---- O-projection (2-product A = attn-out hi/lo): fp32 output ----
__global__ void __launch_bounds__(256, 2) gemm_out(
    const __half* __restrict__ Ah, const __half* __restrict__ Al,
    const __half* __restrict__ B, float* __restrict__ C)
{
    extern __shared__ char smem[];
    const uint32_t sb = smem_u32(smem);
    const int tid = threadIdx.x;
    const int m0 = blockIdx.y * 128, n0 = blockIdx.x * 128;

    float acc[4][4][4];
    #pragma unroll
    for (int i = 0; i < 4; ++i)
        #pragma unroll
        for (int j = 0; j < 4; ++j)
            #pragma unroll
            for (int q = 0; q < 4; ++q) acc[i][j][q] = 0.f;

    gemm_mainloop<2>(Ah, Al, B, sb, tid, m0, n0, acc);
    stage_epilogue(smem, tid, acc);

    float* Cs = (float*)smem;
    const int row  = tid >> 1;
    const int half_ = tid & 1;
    float* dst = C + (size_t)(m0 + row) * DM + n0;
    #pragma unroll
    for (int c0 = 0; c0 < 32; c0 += 4) {
        const int col = half_*32 + c0;
        *(float4*)(dst + col)      = *(float4*)&Cs[row*132 + col];
        *(float4*)(dst + col + 64) = *(float4*)&Cs[row*132 + col + 64];
    }
}

// ---------------------------------------------------- fp16 flash attention --
// q-tile 64, 256 threads / 8 warps (4 rowg x 2 key-half). Single-product fp16
// (Q prescaled). Double-buffered KV, 2-ahead prefetch. 90KB -> 2 CTAs/SM.
// Warp-uniform skip of the oacc rescale when no row max changed.
#define APITCH 272
#define AT_KV   17408             /* buf bs at AT_KV + bs*34816: K, V at +17408 */
#define AT_MASK 87040             /* 2048 bytes (uchar) */
#define AT_RED  89088             /* pmax[64][2], psum[64][2] = 1024B */
#define AT_FLAG 90112             /* per-tile all-valid flags, 64B */
#define AT_SMEM 90176

__global__ void __launch_bounds__(256, 2) attn_mma(
    const __half* __restrict__ Qf, const __half* __restrict__ Kf,
    const __half* __restrict__ Vf, const int* __restrict__ mask,
    __half* __restrict__ Oh, __half* __restrict__ Ol)
{
    extern __shared__ char sm[];
    const uint32_t sb = smem_u32(sm);
    const int tid = threadIdx.x, lane = tid & 31, wid = tid >> 5;
    const int rowg = wid >> 1;            // 0..3: 16-row group
    const int half = wid & 1;             // key half (32 cols)
    const int q0 = (int)(gridDim.x - 1 - blockIdx.x) * 64;   // heavy first
    const int h = blockIdx.y, b = blockIdx.z;
    const size_t hb = ((size_t)(b*NH + h)) * LL * HD;
    const __half *pQ = Qf + hb, *pK = Kf + hb, *pV = Vf + hb;
    unsigned char* msk = (unsigned char*)(sm + AT_MASK);
    float* pmax = (float*)(sm + AT_RED);      // [64][2]
    float* psum = pmax + 128;                 // [64][2]
    unsigned char* tflag = (unsigned char*)(sm + AT_FLAG);

    for (int i = tid; i < LL; i += 256)
        msk[i] = (unsigned char)(mask[b*LL + i] != 0);

    // Q tile (64 rows x 128 hd, single fp16): 4 cp16 per thread
    {
        int row = tid >> 2;
        int c0 = tid & 3;
        const char* gq = (const char*)(pQ + (size_t)(q0+row)*HD);
        uint32_t dq = sb + row * APITCH;
        #pragma unroll
        for (int t = 0; t < 4; ++t) {
            int c = c0 + 4*t;
            cp16(dq + c*16, gq + c*16);
        }
    }

    auto load_kv = [&](int kt, int bs) {
        int k0 = kt * 64;
        int row = tid >> 2;          // 0..63
        int c0 = tid & 3;
        const char* gk = (const char*)(pK + (size_t)(k0+row)*HD);
        const char* gv = (const char*)(pV + (size_t)(k0+row)*HD);
        uint32_t dk = sb + AT_KV + bs*34816 + row*APITCH;
        uint32_t dv = dk + 17408;
        #pragma unroll
        for (int t = 0; t < 4; ++t) {
            int c = c0 + 4*t;
            cp16(dk + c*16, gk + c*16);
            cp16(dv + c*16, gv + c*16);
        }
        cp_commit();
    };

    const int ntiles = q0/64 + 1;
    load_kv(0, 0);
    load_kv((ntiles > 1) ? 1 : 0, 1);   // harmless prefetch when ntiles==1

    __syncthreads();
    if (tid < 32) {
        unsigned char f = 1;
        #pragma unroll 8
        for (int j = 0; j < 64; ++j) f &= msk[tid*64 + j];
        tflag[tid] = f;
    }

    float oacc[16][4];
    #pragma unroll
    for (int u = 0; u < 16; ++u)
        #pragma unroll
        for (int q = 0; q < 4; ++q) oacc[u][q] = 0.f;
    float m_i[2] = {-1e30f, -1e30f}, l_i[2] = {0.f, 0.f};

    const uint32_t a_off = sb + (rowg*16 + (lane & 15))*APITCH + (lane >> 4)*16;
    const uint32_t b_off = (uint32_t)((half*32 + ((lane >> 4) & 1)*8 + (lane & 7))*APITCH
                                      + ((lane >> 3) & 1)*16);
    const uint32_t v_off = (uint32_t)((lane & 15)*APITCH + (lane >> 4)*16);
    const int r0 = lane >> 2;
    const int bar_id = rowg + 1;

    for (int kt = 0; kt < ntiles; ++kt) {
        const int bs = kt & 1;
        const int k0 = kt * 64;
        if (kt == ntiles - 1) cp_wait<0>(); else cp_wait<1>();
        __syncthreads();

        const uint32_t kh_base = sb + AT_KV + bs*34816;
        const uint32_t vh_base = kh_base + 17408;

        // ---- S = Q K^T (single fp16 product; Q prescaled) ----
        float sacc[4][4];
        #pragma unroll
        for (int j = 0; j < 4; ++j)
            #pragma unroll
            for (int q = 0; q < 4; ++q) sacc[j][q] = 0.f;

        #pragma unroll 2
        for (int ks = 0; ks < 8; ++ks) {
            const uint32_t ka = ks * 32;
            uint32_t ah[4], bh[2][4];
            ldm4(ah, a_off + ka);
            ldm4(bh[0], kh_base + b_off + ka);
            ldm4(bh[1], kh_base + b_off + 16*APITCH + ka);
            #pragma unroll
            for (int j = 0; j < 4; ++j)
                mma16816h(sacc[j], ah, &bh[j >> 1][(j & 1) * 2]);
        }

        // ---- softmax: (optional) mask + partial max ----
        const bool needmask = (k0 + 64 > q0) || (tflag[kt] == 0);
        #pragma unroll
        for (int rr = 0; rr < 2; ++rr) {
            const int lr = rowg*16 + r0 + rr*8;
            const int qr = q0 + lr;
            float tm = -1e30f;
            if (needmask) {
                #pragma unroll
                for (int j = 0; j < 4; ++j) {
                    #pragma unroll
                    for (int e = 0; e < 2; ++e) {
                        int col = k0 + half*32 + j*8 + (lane & 3)*2 + e;
                        float v = sacc[j][rr*2 + e];
                        if (col > qr || msk[col] == 0) v = -1e15f;
                        sacc[j][rr*2 + e] = v;
                        tm = fmaxf(tm, v);
                    }
                }
            } else {
                #pragma unroll
                for (int j = 0; j < 4; ++j)
                    tm = fmaxf(tm, fmaxf(sacc[j][rr*2], sacc[j][rr*2 + 1]));
            }
            tm = fmaxf(tm, __shfl_xor_sync(0xffffffffu, tm, 1));
            tm = fmaxf(tm, __shfl_xor_sync(0xffffffffu, tm, 2));
            if ((lane & 3) == 0) pmax[lr*2 + half] = tm;
        }
        asm volatile("bar.sync %0, 64;" :: "r"(bar_id) : "memory");

        // ---- combined max, exp, partial sum ----
        float scv[2];
        #pragma unroll
        for (int rr = 0; rr < 2; ++rr) {
            const int lr = rowg*16 + r0 + rr*8;
            float tm = fmaxf(pmax[lr*2], pmax[lr*2 + 1]);
            float mnew = fmaxf(m_i[rr], tm);
            scv[rr] = __expf(m_i[rr] - mnew);
            m_i[rr] = mnew;
            float rs = 0.f;
            #pragma unroll
            for (int j = 0; j < 4; ++j) {
                #pragma unroll
                for (int e = 0; e < 2; ++e) {
                    float p = __expf(sacc[j][rr*2 + e] - mnew);
                    sacc[j][rr*2 + e] = p;
                    rs += p;
                }
            }
            rs += __shfl_xor_sync(0xffffffffu, rs, 1);
            rs += __shfl_xor_sync(0xffffffffu, rs, 2);
            if ((lane & 3) == 0) psum[lr*2 + half] = rs;
        }
        // rescale oacc only if some row's max actually changed (warp-uniform)
        {
            bool need = (scv[0] != 1.0f) || (scv[1] != 1.0f);
            if (__ballot_sync(0xffffffffu, need) != 0u) {
                #pragma unroll
                for (int u = 0; u < 16; ++u) {
                    oacc[u][0] *= scv[0];
                    oacc[u][1] *= scv[0];
                    oacc[u][2] *= scv[1];
                    oacc[u][3] *= scv[1];
                }
            }
        }
        asm volatile("bar.sync %0, 64;" :: "r"(bar_id) : "memory");

        #pragma unroll
        for (int rr = 0; rr < 2; ++rr) {
            const int lr = rowg*16 + r0 + rr*8;
            l_i[rr] = l_i[rr] * scv[rr] + psum[lr*2] + psum[lr*2 + 1];
        }

        // ---- O += P V over warp's 32 keys (single fp16 product) ----
        #pragma unroll 1
        for (int t = 0; t < 2; ++t) {
            uint32_t pah[4];
            #pragma unroll
            for (int idx = 0; idx < 4; ++idx) {
                int j = 2*t + (idx >> 1);
                int o = (idx & 1) * 2;
                __half2 hv = __floats2half2_rn(sacc[j][o], sacc[j][o + 1]);
                pah[idx] = *(uint32_t*)&hv;
            }
            #pragma unroll
            for (int u = 0; u < 8; ++u) {
                uint32_t vh[4];
                ldm4t(vh, vh_base + (half*32 + t*16)*APITCH + u*32 + v_off);
                mma16816h(oacc[2*u],     pah, vh);
                mma16816h(oacc[2*u + 1], pah, vh + 2);
            }
        }

        __syncthreads();              // all warps done reading buf(bs)
        if (kt + 2 < ntiles) load_kv(kt + 2, bs);
    }

    // ---- combine key-halves via smem (reuse KV buf0), then epilogue ----
    float* Osm = (float*)(sm + AT_KV);      // 64 x 128 fp32 = 32KB
    if (half == 1) {
        #pragma unroll
        for (int rr = 0; rr < 2; ++rr) {
            int r = rowg*16 + r0 + rr*8;
            #pragma unroll
            for (int u = 0; u < 16; ++u) {
                int col = u*8 + (lane & 3)*2;
                Osm[r*128 + col]     = oacc[u][rr*2];
                Osm[r*128 + col + 1] = oacc[u][rr*2 + 1];
            }
        }
    }
    __syncthreads();
    if (half == 0) {
        #pragma unroll
        for (int rr = 0; rr < 2; ++rr) {
            float inv = 1.0f / l_i[rr];
            int r = rowg*16 + r0 + rr*8;
            int lrow = q0 + r;
            size_t base = ((size_t)(b*LL + lrow)) * DM + h*HD;
            #pragma unroll
            for (int u = 0; u < 16; ++u) {
                int col = u*8 + (lane & 3)*2;
                float p0 = (oacc[u][rr*2]     + Osm[r*128 + col])     * inv;
                float p1 = (oacc[u][rr*2 + 1] + Osm[r*128 + col + 1]) * inv;
                __half2 hv = __floats2half2_rn(p0, p1);
                float2 hf = __half22float2(hv);
                __half2 lv = __floats2half2_rn(p0 - hf.x, p1 - hf.y);
                *(__half2*)(Oh + base + col) = hv;
                *(__half2*)(Ol + base + col) = lv;
            }
        }
    }
}

// ---------------------------------------------------------------------------
extern "C" void kernel_launch(void* const* d_in, const int* in_sizes, int n_in,
                              void* d_out, int out_size)
{
    const float* hidden = (const float*)d_in[0];
    const int*   mask   = (const int*)  d_in[1];
    const float* Wq     = (const float*)d_in[2];
    const float* Wk     = (const float*)d_in[3];
    const float* Wv     = (const float*)d_in[4];
    const float* Wo     = (const float*)d_in[5];
    const float* cosc   = (const float*)d_in[6];
    const float* sinc   = (const float*)d_in[7];
    float* out = (float*)d_out;

    __half *Ahp, *Alp, *W4p, *Qfp, *Kfp, *Vfp;
    cudaGetSymbolAddress((void**)&Ahp, g_Ah);
    cudaGetSymbolAddress((void**)&Alp, g_Al);
    cudaGetSymbolAddress((void**)&W4p, g_W4);
    cudaGetSymbolAddress((void**)&Qfp, g_Qf);
    cudaGetSymbolAddress((void**)&Kfp, g_Kf);
    cudaGetSymbolAddress((void**)&Vfp, g_Vf);

    cudaFuncSetAttribute(gemm_qkv, cudaFuncAttributeMaxDynamicSharedMemorySize, GSMEM);
    cudaFuncSetAttribute(gemm_out, cudaFuncAttributeMaxDynamicSharedMemorySize, GSMEM);
    cudaFuncSetAttribute(attn_mma, cudaFuncAttributeMaxDynamicSharedMemorySize, AT_SMEM);

    const int nA4 = MROWS*DM/4, nW4 = DM*DM/4;

    cvt1_kernel<<<(nA4+255)/256, 256>>>(hidden, Ahp, nA4);
    {
        dim3 gs((nW4+255)/256, 4);
        cvtW_kernel<<<gs, 256>>>(Wq, Wk, Wv, Wo, W4p, nW4);
    }

    {
        dim3 gg(DM/128, MROWS/128, 3);
        gemm_qkv<<<gg, 256, GSMEM>>>(Ahp, W4p, Qfp, Kfp, Vfp, cosc, sinc);
    }

    dim3 ga(LL/64, NH, BB);
    attn_mma<<<ga, 256, AT_SMEM>>>(Qfp, Kfp, Vfp, mask, Ahp, Alp);

    {
        dim3 gg(DM/128, MROWS/128);
        gemm_out<<<gg, 256, GSMEM>>>(Ahp, Alp, W4p + 3*WSZ, out);
    }
}